// round 13
// baseline (speedup 1.0000x reference)
#include <cuda_runtime.h>
#include <cuda_bf16.h>
#include <cstddef>
#include <cstdint>

// ---------------- problem constants ----------------
#define U_  1024
#define B_  8
#define D_  512
#define H_  8
#define HD_ 64
#define CL_ 64
#define RC_ 4
#define C_  16
#define R_  64
#define S_  16
#define M_  15
#define Q_  1104
#define KV_ 1103
#define NEG_INF_ (-100000000.0f)
#define SCALING_ 0.125f

typedef unsigned long long u64t;

// ---------------- mma / async helpers ----------------
__device__ __forceinline__ uint32_t smem_u32(const void* p) {
    uint32_t a;
    asm("{ .reg .u64 t; cvta.to.shared.u64 t, %1; cvt.u32.u64 %0, t; }" : "=r"(a) : "l"(p));
    return a;
}
#define SWZ128(o) ((o) ^ (((o) >> 3) & 0x70))

__device__ __forceinline__ void ldmx4(uint32_t* r, uint32_t addr) {
    asm volatile("ldmatrix.sync.aligned.m8n8.x4.shared.b16 {%0,%1,%2,%3}, [%4];"
                 : "=r"(r[0]), "=r"(r[1]), "=r"(r[2]), "=r"(r[3]) : "r"(addr));
}
__device__ __forceinline__ void ldmx4t(uint32_t* r, uint32_t addr) {
    asm volatile("ldmatrix.sync.aligned.m8n8.x4.trans.shared.b16 {%0,%1,%2,%3}, [%4];"
                 : "=r"(r[0]), "=r"(r[1]), "=r"(r[2]), "=r"(r[3]) : "r"(addr));
}
__device__ __forceinline__ void mma16816(float* d, const uint32_t* a,
                                         uint32_t b0, uint32_t b1) {
    asm volatile(
        "mma.sync.aligned.m16n8k16.row.col.f32.bf16.bf16.f32 "
        "{%0,%1,%2,%3}, {%4,%5,%6,%7}, {%8,%9}, {%0,%1,%2,%3};"
        : "+f"(d[0]), "+f"(d[1]), "+f"(d[2]), "+f"(d[3])
        : "r"(a[0]), "r"(a[1]), "r"(a[2]), "r"(a[3]), "r"(b0), "r"(b1));
}
__device__ __forceinline__ void cpa16(uint32_t dst, const void* src) {
    asm volatile("cp.async.cg.shared.global [%0], [%1], 16;" :: "r"(dst), "l"(src));
}
#define CPA_COMMIT() asm volatile("cp.async.commit_group;" ::: "memory")
#define CPA_WAIT1()  asm volatile("cp.async.wait_group 1;" ::: "memory")
#define CPA_WAIT0()  asm volatile("cp.async.wait_group 0;" ::: "memory")

// pack two floats into bf16x2 hi and lo words
__device__ __forceinline__ void pack_hl(float x, float y, uint32_t& hi, uint32_t& lo) {
    __nv_bfloat16 h0 = __float2bfloat16(x), h1 = __float2bfloat16(y);
    __nv_bfloat16 l0 = __float2bfloat16(x - __bfloat162float(h0));
    __nv_bfloat16 l1 = __float2bfloat16(y - __bfloat162float(h1));
    hi = (uint32_t)__bfloat16_as_ushort(h0) | ((uint32_t)__bfloat16_as_ushort(h1) << 16);
    lo = (uint32_t)__bfloat16_as_ushort(l0) | ((uint32_t)__bfloat16_as_ushort(l1) << 16);
}

// ---------------- scratch (device globals; no allocs) ----------------
__device__ float g_q[(size_t)Q_ * B_ * D_];
__device__ float g_kv[(size_t)KV_ * B_ * 2 * D_];
__device__ float g_pos[(size_t)192 * D_];
__device__ float g_attn[(size_t)Q_ * B_ * D_];
__device__ float g_ps[(size_t)64 * 1024 * 192];     // posS = (q_utt+pbv).pos^T
// weights: W_q 0..511 | W_kv 512..1535 | W_out 1536..2047 | W_pos 2048..2559
__device__ __nv_bfloat16 g_whi[(size_t)2560 * 512];
__device__ __nv_bfloat16 g_wlo[(size_t)2560 * 512];
// A concat: [mem|rc|utt|summ|pos]; rows 0..8703 overwritten by attention output
__device__ __nv_bfloat16 g_ahi[(size_t)9216 * 512];
__device__ __nv_bfloat16 g_alo[(size_t)9216 * 512];
__device__ __nv_bfloat16 g_poshi[(size_t)192 * 512];
__device__ __nv_bfloat16 g_poslo[(size_t)192 * 512];

__device__ __forceinline__ int kv_row_of(int i, int c, int ustart) {
    return (i < c) ? i
         : (i < c + 4 ? M_ + c * 4 + (i - c)
                      : M_ + R_ + ustart + (i - c - 4));
}

// =====================================================================
// All-weights split
// =====================================================================
__global__ void conv_w_all(const float* __restrict__ Wq, const float* __restrict__ Wkv,
                           const float* __restrict__ Wout, const float* __restrict__ Wpos)
{
    int i = blockIdx.x * 256 + threadIdx.x;
    int row = i >> 9, col = i & 511;
    const float* src; int lr;
    if (row < 512)       { src = Wq;   lr = row; }
    else if (row < 1536) { src = Wkv;  lr = row - 512; }
    else if (row < 2048) { src = Wout; lr = row - 1536; }
    else                 { src = Wpos; lr = row - 2048; }
    float a = src[(size_t)lr * 512 + col];
    __nv_bfloat16 h = __float2bfloat16(a);
    g_whi[i] = h;
    g_wlo[i] = __float2bfloat16(a - __bfloat162float(h));
}

// =====================================================================
// A split (concat of <=4 row segments)
// =====================================================================
__global__ void conv_a_kernel(const float* __restrict__ A0, const float* __restrict__ A1,
                              const float* __restrict__ A2, const float* __restrict__ A3,
                              int r1, int r2, int r3, int nrows, int dst_row0)
{
    int i = blockIdx.x * 256 + threadIdx.x;
    if (i >= nrows * 128) return;
    int row = i >> 7, c4 = (i & 127) * 4;
    const float* src; int lr;
    if (row < r1)      { src = A0; lr = row; }
    else if (row < r2) { src = A1; lr = row - r1; }
    else if (row < r3) { src = A2; lr = row - r2; }
    else               { src = A3; lr = row - r3; }
    float4 v = *(const float4*)(src + (size_t)lr * 512 + c4);
    uint32_t h0, l0, h1, l1;
    pack_hl(v.x, v.y, h0, l0);
    pack_hl(v.z, v.w, h1, l1);
    size_t o = (size_t)(dst_row0 + row) * 512 + c4;
    *(uint2*)&g_ahi[o] = make_uint2(h0, h1);
    *(uint2*)&g_alo[o] = make_uint2(l0, l1);
}

// =====================================================================
// pos split: g_pos (192x512 fp32; row 191 zero) -> g_poshi/g_poslo
// =====================================================================
__global__ void conv_pos_kernel()
{
    int i = blockIdx.x * 256 + threadIdx.x;
    if (i >= 192 * 256) return;
    int row = i >> 8, c2 = (i & 255) * 2;
    float2 v = *(const float2*)(g_pos + (size_t)row * 512 + c2);
    uint32_t hi, lo;
    pack_hl(v.x, v.y, hi, lo);
    *(uint32_t*)&g_poshi[(size_t)row * 512 + c2] = hi;
    *(uint32_t*)&g_poslo[(size_t)row * 512 + c2] = lo;
}

// =====================================================================
// GEMM mainloop: 128x128 tile, cp.async 3-stage, 24 chunks
// =====================================================================
#define GSM_TOTAL 98304

#define GEMM_MAINLOOP(AHI, ALO, WHI, WLO, MRTOT)                                    \
    float acc[2][8][4] = {};                                                        \
    {                                                                               \
        auto issue = [&](int cc) {                                                  \
            const int seg = cc >> 3;                                                \
            const int k0 = (cc & 7) * 64;                                           \
            const __nv_bfloat16* asrc = (seg == 1) ? (ALO) : (AHI);                 \
            const __nv_bfloat16* wsrc = (seg == 2) ? (WLO) : (WHI);                 \
            char* abuf = gsm + (cc % 3) * 16384;                                    \
            char* bbuf = gsm + 49152 + (cc % 3) * 16384;                            \
            _Pragma("unroll")                                                       \
            for (int t = 0; t < 4; t++) {                                           \
                int ar = car + t * 32;                                              \
                int gr = row0 + ar; if (gr >= (MRTOT)) gr = (MRTOT) - 1;            \
                cpa16(smem_u32(abuf) + SWZ128((uint32_t)(ar * 128 + cg8 * 16)),     \
                      asrc + (size_t)gr * 512 + k0 + cg8 * 8);                      \
            }                                                                       \
            _Pragma("unroll")                                                       \
            for (int t = 0; t < 4; t++) {                                           \
                int br = car + t * 32;                                              \
                cpa16(smem_u32(bbuf) + SWZ128((uint32_t)(br * 128 + cg8 * 16)),     \
                      wsrc + (size_t)(col0 + br) * 512 + k0 + cg8 * 8);             \
            }                                                                       \
            CPA_COMMIT();                                                           \
        };                                                                          \
        issue(0);                                                                   \
        issue(1);                                                                   \
        const int l15 = lane & 15, lh = lane >> 4;                                  \
        const int l8 = lane & 7, lg = lane >> 3;                                    \
        for (int cc = 0; cc < 24; cc++) {                                           \
            if (cc < 23) CPA_WAIT1(); else CPA_WAIT0();                             \
            __syncthreads();                                                        \
            const uint32_t Ab = sb + (cc % 3) * 16384;                              \
            const uint32_t Bb = sb + 49152 + (cc % 3) * 16384;                      \
            _Pragma("unroll")                                                       \
            for (int s = 0; s < 4; s++) {                                           \
                uint32_t afr[2][4];                                                 \
                _Pragma("unroll")                                                   \
                for (int mt = 0; mt < 2; mt++) {                                    \
                    int r = wm * 32 + mt * 16 + l15;                                \
                    ldmx4(afr[mt], Ab + SWZ128((uint32_t)(r * 128 + s * 32 + lh * 16))); \
                }                                                                   \
                uint32_t bfr[4][4];                                                 \
                _Pragma("unroll")                                                   \
                for (int bt = 0; bt < 4; bt++) {                                    \
                    int n = wn * 64 + bt * 16 + ((lg >> 1) ? 8 : 0) + l8;           \
                    ldmx4(bfr[bt], Bb + SWZ128((uint32_t)(n * 128 + s * 32 + (lg & 1) * 16))); \
                }                                                                   \
                _Pragma("unroll")                                                   \
                for (int mt = 0; mt < 2; mt++)                                      \
                    _Pragma("unroll")                                               \
                    for (int nt = 0; nt < 8; nt++) {                                \
                        int bt = nt >> 1, sub = nt & 1;                             \
                        mma16816(acc[mt][nt], afr[mt], bfr[bt][2*sub], bfr[bt][2*sub+1]); \
                    }                                                               \
            }                                                                       \
            if (cc + 2 < 24) issue(cc + 2);                                         \
        }                                                                           \
    }

// ---- generic GEMM (pos / out projections) ----
__global__ __launch_bounds__(256, 2) void gemm_tc_kernel(
    const __nv_bfloat16* __restrict__ Ahi, const __nv_bfloat16* __restrict__ Alo,
    const __nv_bfloat16* __restrict__ Whib, const __nv_bfloat16* __restrict__ Wlob,
    float* __restrict__ Cm, int Mr, int ldc, const float* __restrict__ bias)
{
    extern __shared__ char gsm[];
    const uint32_t sb = smem_u32(gsm);
    const int tid = threadIdx.x;
    const int wid = tid >> 5, lane = tid & 31;
    const int wm = wid & 3, wn = wid >> 2;
    const int row0 = blockIdx.y * 128, col0 = blockIdx.x * 128;
    const int car = tid >> 3, cg8 = tid & 7;

    GEMM_MAINLOOP(Ahi, Alo, Whib, Wlob, Mr)

    const int quad = lane >> 2, tq = lane & 3;
    #pragma unroll
    for (int mt = 0; mt < 2; mt++) {
        #pragma unroll
        for (int nt = 0; nt < 8; nt++) {
            int gr0 = row0 + wm * 32 + mt * 16 + quad;
            int gc  = col0 + wn * 64 + nt * 8 + tq * 2;
            float b0 = bias ? bias[gc]     : 0.f;
            float b1 = bias ? bias[gc + 1] : 0.f;
            #pragma unroll
            for (int half = 0; half < 2; half++) {
                int gr = gr0 + half * 8;
                if (gr < Mr) {
                    float2 v = {acc[mt][nt][half*2+0] + b0, acc[mt][nt][half*2+1] + b1};
                    *(float2*)&Cm[(size_t)gr * ldc + gc] = v;
                }
            }
        }
    }
}

// ---- fused Q+KV GEMM ----
__global__ __launch_bounds__(256, 2) void gemm_qkv_kernel(
    const float* __restrict__ b_q, const float* __restrict__ b_kv)
{
    extern __shared__ char gsm[];
    const uint32_t sb = smem_u32(gsm);
    const int tid = threadIdx.x;
    const int wid = tid >> 5, lane = tid & 31;
    const int wm = wid & 3, wn = wid >> 2;
    const int row0 = blockIdx.y * 128, col0 = blockIdx.x * 128;
    const int car = tid >> 3, cg8 = tid & 7;

    GEMM_MAINLOOP(g_ahi, g_alo, g_whi, g_wlo, 8952)

    const int quad = lane >> 2, tq = lane & 3;
    const bool is_q = (col0 < 512);
    #pragma unroll
    for (int mt = 0; mt < 2; mt++) {
        #pragma unroll
        for (int nt = 0; nt < 8; nt++) {
            int gr0 = row0 + wm * 32 + mt * 16 + quad;
            int gc  = col0 + wn * 64 + nt * 8 + tq * 2;
            #pragma unroll
            for (int half = 0; half < 2; half++) {
                int gr = gr0 + half * 8;
                if (gr >= 8952) continue;
                float2 v = {acc[mt][nt][half*2+0], acc[mt][nt][half*2+1]};
                if (is_q) {
                    int qr = gr - 120;
                    if (qr >= 0) {
                        v.x += b_q[gc]; v.y += b_q[gc + 1];
                        *(float2*)&g_q[(size_t)qr * 512 + gc] = v;
                    }
                } else {
                    int kc = gc - 512;
                    if (gr < 8824) {
                        v.x += b_kv[kc]; v.y += b_kv[kc + 1];
                        *(float2*)&g_kv[(size_t)gr * 1024 + kc] = v;
                    }
                }
            }
        }
    }
}

// =====================================================================
// ps kernel: g_ps[bh][u][pl] = (q_utt + pbv).pos^T via HMMA (3 passes).
// grid (16 u-tiles of 64, 64 bh), 256 threads, 64KB smem -> 2 CTA/SM.
// smem: QHI 0 (64x128B), QLO 8192, PH 16384 (192x128B), PL 40960
// =====================================================================
#define PS_TOTAL 65536

__global__ __launch_bounds__(256) void ps_kernel(const float* __restrict__ pbv)
{
    extern __shared__ char psm[];
    const uint32_t sb = smem_u32(psm);
    const int ut = blockIdx.x, bh = blockIdx.y;
    const int b = bh >> 3, h = bh & 7;
    const int tid = threadIdx.x;
    const int wid = tid >> 5, lane = tid & 31;

    // cp.async pos rows (192, hi/lo)
    for (int idx = tid; idx < 192 * 8; idx += 256) {
        int r = idx >> 3, ch = idx & 7;
        size_t go = (size_t)r * 512 + h * 64 + ch * 8;
        uint32_t so = SWZ128((uint32_t)(r * 128 + ch * 16));
        cpa16(sb + 16384 + so, g_poshi + go);
        cpa16(sb + 40960 + so, g_poslo + go);
    }
    CPA_COMMIT();

    // convert Q rows (64): q + pbv
    for (int idx = tid; idx < 64 * 32; idx += 256) {
        int r = idx >> 5, pr = idx & 31;
        int qrow = R_ + ut * 64 + r;
        float2 v = *(const float2*)(g_q + ((size_t)qrow * B_ + b) * 512 + h * 64 + pr * 2);
        v.x += pbv[h * 64 + pr * 2];
        v.y += pbv[h * 64 + pr * 2 + 1];
        uint32_t vhi, vlo;
        pack_hl(v.x, v.y, vhi, vlo);
        uint32_t off = SWZ128((uint32_t)(r * 128 + pr * 4));
        *(uint32_t*)(psm + off) = vhi;
        *(uint32_t*)(psm + 8192 + off) = vlo;
    }
    CPA_WAIT0();
    __syncthreads();

    const int wm = wid >> 2, wn = wid & 3;
    const int l15 = lane & 15, lh = lane >> 4;
    const int l8 = lane & 7, lg = lane >> 3;
    const int quad = lane >> 2, tq = lane & 3;

    float acc[2][3][2][4] = {};
    #pragma unroll
    for (int pass = 0; pass < 3; pass++) {
        const uint32_t Ab = sb + ((pass == 1) ? 8192 : 0);
        const uint32_t Bb = sb + ((pass == 2) ? 40960 : 16384);
        #pragma unroll
        for (int s = 0; s < 4; s++) {
            uint32_t afr[2][4];
            #pragma unroll
            for (int mi = 0; mi < 2; mi++) {
                int r = (wm * 2 + mi) * 16 + l15;
                ldmx4(afr[mi], Ab + SWZ128((uint32_t)(r * 128 + s * 32 + lh * 16)));
            }
            #pragma unroll
            for (int nj = 0; nj < 3; nj++) {
                uint32_t bfr[4];
                int n = (wn + 4 * nj) * 16 + ((lg >> 1) ? 8 : 0) + l8;
                ldmx4(bfr, Bb + SWZ128((uint32_t)(n * 128 + s * 32 + (lg & 1) * 16)));
                #pragma unroll
                for (int mi = 0; mi < 2; mi++) {
                    mma16816(acc[mi][nj][0], afr[mi], bfr[0], bfr[1]);
                    mma16816(acc[mi][nj][1], afr[mi], bfr[2], bfr[3]);
                }
            }
        }
    }
    // epilogue -> g_ps
    #pragma unroll
    for (int mi = 0; mi < 2; mi++) {
        #pragma unroll
        for (int nj = 0; nj < 3; nj++) {
            #pragma unroll
            for (int nh = 0; nh < 2; nh++) {
                int col = (wn + 4 * nj) * 16 + nh * 8 + tq * 2;
                #pragma unroll
                for (int hf = 0; hf < 2; hf++) {
                    int r = (wm * 2 + mi) * 16 + quad + hf * 8;
                    int u = ut * 64 + r;
                    *(float2*)&g_ps[((size_t)bh * 1024 + u) * 192 + col] =
                        make_float2(acc[mi][nj][nh][hf * 2 + 0], acc[mi][nj][nh][hf * 2 + 1]);
                }
            }
        }
    }
}

// =====================================================================
// Fused attention v6: HMMA C1 (pbu folded) + softmax(+g_ps band) + HMMA PV
// 512 threads, 113280B smem -> 2 CTAs/SM.
// smem: QHI 0 (10240) QLO 10240 | KHI 20480 KLO 40960 (V reuses)
//       SS 61440 (fp32 stride 648B, 80 rows) ; P overlays: PHI 61440, PLO 84624 (stride 336B)
// =====================================================================
#define FZ_QHI 0
#define FZ_QLO 10240
#define FZ_KHI 20480
#define FZ_KLO 40960
#define FZ_SS  61440
#define FZ_PHI 61440
#define FZ_PLO 84624
#define FZ_TOTAL 113280

__global__ __launch_bounds__(512, 2) void fused_attn_kernel(
    const int* __restrict__ lengths, const float* __restrict__ pbu)
{
    extern __shared__ char fsm[];
    const uint32_t sb = smem_u32(fsm);

    const int c = blockIdx.x, bh = blockIdx.y;
    const int b = bh >> 3, h = bh & 7;
    const int tid = threadIdx.x;
    const int wid = tid >> 5, lane = tid & 31;
    const int ustart = (c == 0) ? 0 : (c - 1) * CL_;
    const int ncols = c + 4 + ((c == 0) ? 64 : 128);
    const int len_b = lengths[b];
    const int pbase = (c == 0) ? 127 : 63;

    // ---- convert Q (80 rows) fp32 (+pbu) -> bf16 hi/lo SW128 smem ----
    for (int idx = tid; idx < 80 * 32; idx += 512) {
        int r = idx >> 5, pr = idx & 31;
        uint32_t vhi = 0, vlo = 0;
        if (r < 69) {
            int qrow = (r < 4) ? c * 4 + r
                     : (r < 68 ? R_ + c * 64 + (r - 4) : R_ + U_ + c);
            float2 v = *(const float2*)(g_q + ((size_t)qrow * B_ + b) * 512 + h * 64 + pr * 2);
            v.x += pbu[h * 64 + pr * 2];
            v.y += pbu[h * 64 + pr * 2 + 1];
            pack_hl(v.x, v.y, vhi, vlo);
        }
        uint32_t off = SWZ128((uint32_t)(r * 128 + pr * 4));
        *(uint32_t*)(fsm + FZ_QHI + off) = vhi;
        *(uint32_t*)(fsm + FZ_QLO + off) = vlo;
    }
    // ---- convert K (160 rows) ----
    for (int idx = tid; idx < 160 * 32; idx += 512) {
        int r = idx >> 5, pr = idx & 31;
        uint32_t vhi = 0, vlo = 0;
        if (r < ncols) {
            int kvrow = kv_row_of(r, c, ustart);
            float2 v = *(const float2*)(g_kv + ((size_t)kvrow * B_ + b) * 1024 + h * 64 + pr * 2);
            pack_hl(v.x, v.y, vhi, vlo);
        }
        uint32_t off = SWZ128((uint32_t)(r * 128 + pr * 4));
        *(uint32_t*)(fsm + FZ_KHI + off) = vhi;
        *(uint32_t*)(fsm + FZ_KLO + off) = vlo;
    }
    __syncthreads();

    const int l15 = lane & 15, lh = lane >> 4;
    const int l8 = lane & 7, lg = lane >> 3;
    const int quad = lane >> 2, tq = lane & 3;
    const int wmc = wid / 3, wnc = wid % 3;   // wid 15 -> wmc 5 inactive

    // ---- C1: scores = (Q+pbu).K^T (HMMA, 3 passes) ----
    if (wmc < 5) {
        float acc[4][2][4] = {};
        #pragma unroll
        for (int pass = 0; pass < 3; pass++) {
            const uint32_t Ab = sb + ((pass == 1) ? FZ_QLO : FZ_QHI);
            const uint32_t Bb = sb + ((pass == 2) ? FZ_KLO : FZ_KHI);
            #pragma unroll
            for (int s = 0; s < 4; s++) {
                uint32_t afr[4];
                ldmx4(afr, Ab + SWZ128((uint32_t)((wmc * 16 + l15) * 128 + s * 32 + lh * 16)));
                #pragma unroll
                for (int nj = 0; nj < 4; nj++) {
                    int nt = wnc + 3 * nj;
                    if (nt < 10) {
                        uint32_t bfr[4];
                        int n = nt * 16 + ((lg >> 1) ? 8 : 0) + l8;
                        ldmx4(bfr, Bb + SWZ128((uint32_t)(n * 128 + s * 32 + (lg & 1) * 16)));
                        mma16816(acc[nj][0], afr, bfr[0], bfr[1]);
                        mma16816(acc[nj][1], afr, bfr[2], bfr[3]);
                    }
                }
            }
        }
        #pragma unroll
        for (int nj = 0; nj < 4; nj++) {
            int nt = wnc + 3 * nj;
            if (nt < 10) {
                int r0 = wmc * 16 + quad;
                #pragma unroll
                for (int hf = 0; hf < 2; hf++) {
                    int col = nt * 16 + hf * 8 + tq * 2;
                    *(float2*)(fsm + FZ_SS + (size_t)r0 * 648 + col * 4) =
                        make_float2(acc[nj][hf][0], acc[nj][hf][1]);
                    *(float2*)(fsm + FZ_SS + (size_t)(r0 + 8) * 648 + col * 4) =
                        make_float2(acc[nj][hf][2], acc[nj][hf][3]);
                }
            }
        }
    }
    __syncthreads();

    // ---- V conversion (overwrites K region) + softmax phase A ----
    float pvals[5][5];
    {
        for (int idx = tid; idx < 160 * 32; idx += 512) {
            int r = idx >> 5, pr = idx & 31;
            uint32_t vhi = 0, vlo = 0;
            if (r < ncols) {
                int kvrow = kv_row_of(r, c, ustart);
                float2 v = *(const float2*)(g_kv + ((size_t)kvrow * B_ + b) * 1024 + 512 + h * 64 + pr * 2);
                pack_hl(v.x, v.y, vhi, vlo);
            }
            uint32_t off = SWZ128((uint32_t)(r * 128 + pr * 4));
            *(uint32_t*)(fsm + FZ_KHI + off) = vhi;
            *(uint32_t*)(fsm + FZ_KLO + off) = vlo;
        }
        const int limit_j = len_b - ustart;
        const int uc0 = c + 4;
        int slot = 0;
        for (int r = wid; r < 69; r += 16, slot++) {
            const bool is_utt = (r >= 4) && (r < 68);
            const int u_loc = r - 4;
            const float* psrow = g_ps + ((size_t)bh * 1024 + c * 64 + u_loc) * 192;
            const int plb = pbase - u_loc - uc0;   // pl = plb + i
            float vals[5];
            float mx = -3.4e38f;
            #pragma unroll
            for (int g = 0; g < 5; g++) {
                int i = lane + 32 * g;
                float v = -3.4e38f;
                if (i < ncols) {
                    float s = *(const float*)(fsm + FZ_SS + (size_t)r * 648 + i * 4);
                    if (i >= uc0) {
                        int j = i - uc0;
                        if (is_utt) s += psrow[plb + i];
                        v = (j >= limit_j) ? NEG_INF_ : s * SCALING_;
                    } else {
                        v = s * SCALING_;
                    }
                }
                vals[g] = v;
                mx = fmaxf(mx, v);
            }
            #pragma unroll
            for (int o = 16; o > 0; o >>= 1) mx = fmaxf(mx, __shfl_xor_sync(~0u, mx, o));
            float sum = 0.f;
            #pragma unroll
            for (int g = 0; g < 5; g++) {
                float e = __expf(vals[g] - mx);
                vals[g] = e;
                sum += e;
            }
            #pragma unroll
            for (int o = 16; o > 0; o >>= 1) sum += __shfl_xor_sync(~0u, sum, o);
            float inv = 1.f / sum;
            #pragma unroll
            for (int g = 0; g < 5; g++) pvals[slot][g] = vals[g] * inv;
        }
    }
    __syncthreads();

    // ---- phase B: write P bf16 hi/lo over dead score region (no zeroing:
    //      garbage P rows >=69 only feed output rows that are never stored) ----
    {
        int slot = 0;
        for (int r = wid; r < 69; r += 16, slot++) {
            #pragma unroll
            for (int g = 0; g < 5; g++) {
                int i = lane + 32 * g;
                float p = (i < ncols) ? pvals[slot][g] : 0.f;
                __nv_bfloat16 hp = __float2bfloat16(p);
                __nv_bfloat16 lp = __float2bfloat16(p - __bfloat162float(hp));
                *(ushort*)(fsm + FZ_PHI + r * 336 + i * 2) = __bfloat16_as_ushort(hp);
                *(ushort*)(fsm + FZ_PLO + r * 336 + i * 2) = __bfloat16_as_ushort(lp);
            }
        }
    }
    __syncthreads();

    // ---- PV: out = P.V (HMMA, 3 passes) ----
    {
        const int wmp = wid >> 2, wnp = wid & 3;
        float accp[2][2][4] = {};
        #pragma unroll
        for (int pass = 0; pass < 3; pass++) {
            const uint32_t Ab = sb + ((pass == 1) ? FZ_PLO : FZ_PHI);
            const uint32_t Bb = sb + ((pass == 2) ? FZ_KLO : FZ_KHI);
            #pragma unroll
            for (int kk = 0; kk < 10; kk++) {
                uint32_t bfr[4];
                ldmx4t(bfr, Bb + SWZ128((uint32_t)((kk * 16 + l15) * 128 + wnp * 32 + lh * 16)));
                #pragma unroll
                for (int mi = 0; mi < 2; mi++) {
                    int m = wmp + 4 * mi;
                    if (m < 5) {
                        uint32_t afr[4];
                        ldmx4(afr, Ab + (uint32_t)((m * 16 + l15) * 336 + kk * 32 + lh * 16));
                        mma16816(accp[mi][0], afr, bfr[0], bfr[1]);
                        mma16816(accp[mi][1], afr, bfr[2], bfr[3]);
                    }
                }
            }
        }
        #pragma unroll
        for (int mi = 0; mi < 2; mi++) {
            int m = wmp + 4 * mi;
            if (m >= 5) continue;
            int r0 = m * 16 + quad;
            #pragma unroll
            for (int hf = 0; hf < 2; hf++) {
                int r = r0 + hf * 8;
                if (r < 68) {
                    int qrow = (r < 4) ? c * 4 + r : R_ + c * 64 + (r - 4);
                    size_t base = ((size_t)qrow * B_ + b) * 512 + h * 64;
                    #pragma unroll
                    for (int n = 0; n < 2; n++) {
                        int d = wnp * 16 + n * 8 + tq * 2;
                        uint32_t vhi, vlo;
                        pack_hl(accp[mi][n][hf*2+0], accp[mi][n][hf*2+1], vhi, vlo);
                        *(uint32_t*)&g_ahi[base + d] = vhi;
                        *(uint32_t*)&g_alo[base + d] = vlo;
                    }
                } else if (r == 68) {
                    int qrow = R_ + U_ + c;
                    float* dst = g_attn + ((size_t)qrow * B_ + b) * 512 + h * 64;
                    #pragma unroll
                    for (int n = 0; n < 2; n++) {
                        int d = wnp * 16 + n * 8 + tq * 2;
                        *(float2*)(dst + d) =
                            make_float2(accp[mi][n][hf*2+0], accp[mi][n][hf*2+1]);
                    }
                }
            }
        }
    }
}

// ---------------- out_mem = clip(attn[R+U:], -10, 10) ----------------
__global__ void clip_kernel(float* __restrict__ out)
{
    const size_t off = (size_t)(R_ + U_) * B_ * D_;
    int i = blockIdx.x * 256 + threadIdx.x;
    float v = g_attn[off + i];
    out[off + i] = fminf(10.f, fmaxf(-10.f, v));
}

// ---------------- launch ----------------
extern "C" void kernel_launch(void* const* d_in, const int* in_sizes, int n_in,
                              void* d_out, int out_size)
{
    const float* utt    = (const float*)d_in[0];
    const int*   lens   = (const int*)  d_in[1];
    const float* rc     = (const float*)d_in[2];
    const float* summ   = (const float*)d_in[3];
    const float* mem    = (const float*)d_in[4];
    const float* pos_e  = (const float*)d_in[6];
    const float* W_kv   = (const float*)d_in[7];
    const float* b_kv   = (const float*)d_in[8];
    const float* W_q    = (const float*)d_in[9];
    const float* b_q    = (const float*)d_in[10];
    const float* W_out  = (const float*)d_in[11];
    const float* b_out  = (const float*)d_in[12];
    const float* W_pos  = (const float*)d_in[13];
    const float* pbu    = (const float*)d_in[14];
    const float* pbv    = (const float*)d_in[15];
    float* out = (float*)d_out;

    float *pos_buf;
    __nv_bfloat16 *ahi, *alo, *whi, *wlo;
    cudaGetSymbolAddress((void**)&pos_buf, g_pos);
    cudaGetSymbolAddress((void**)&ahi,     g_ahi);
    cudaGetSymbolAddress((void**)&alo,     g_alo);
    cudaGetSymbolAddress((void**)&whi,     g_whi);
    cudaGetSymbolAddress((void**)&wlo,     g_wlo);

    cudaFuncSetAttribute(fused_attn_kernel,
                         cudaFuncAttributeMaxDynamicSharedMemorySize, FZ_TOTAL);
    cudaFuncSetAttribute(ps_kernel,
                         cudaFuncAttributeMaxDynamicSharedMemorySize, PS_TOTAL);
    cudaFuncSetAttribute(gemm_tc_kernel,
                         cudaFuncAttributeMaxDynamicSharedMemorySize, GSM_TOTAL);
    cudaFuncSetAttribute(gemm_qkv_kernel,
                         cudaFuncAttributeMaxDynamicSharedMemorySize, GSM_TOTAL);

    const dim3 blk(256);
    const float* pos_src = pos_e + (size_t)(U_ - 128) * D_;

    // ---- conversions ----
    conv_a_kernel<<<dim3((8952 * 128 + 255) / 256), blk>>>(
        mem, rc, utt, summ, 120, 632, 8824, 8952, 0);
    conv_a_kernel<<<dim3((191 * 128 + 255) / 256), blk>>>(
        pos_src, pos_src, pos_src, pos_src, 191, 191, 191, 191, 8952);
    conv_w_all<<<dim3(2560 * 512 / 256), blk>>>(W_q, W_kv, W_out, W_pos);

    // ---- fused Q+KV projection ----
    gemm_qkv_kernel<<<dim3(12, 70), blk, GSM_TOTAL>>>(b_q, b_kv);

    // ---- pos projection (fp32 out) then bf16 split ----
    gemm_tc_kernel<<<dim3(4, 2), blk, GSM_TOTAL>>>(
        ahi + (size_t)8952 * 512, alo + (size_t)8952 * 512,
        whi + (size_t)2048 * 512, wlo + (size_t)2048 * 512,
        pos_buf, 191, D_, nullptr);
    conv_pos_kernel<<<dim3(192), blk>>>();

    // ---- posS then fused attention ----
    ps_kernel<<<dim3(16, 64), blk, PS_TOTAL>>>(pbv);
    fused_attn_kernel<<<dim3(C_, 64), dim3(512), FZ_TOTAL>>>(lens, pbu);

    // ---- output projection ----
    gemm_tc_kernel<<<dim3(4, 68), blk, GSM_TOTAL>>>(
        ahi, alo, whi + (size_t)1536 * 512, wlo + (size_t)1536 * 512,
        out, (R_ + U_) * B_, D_, b_out);
    clip_kernel<<<dim3(256), blk>>>(out);
}

// round 14
// speedup vs baseline: 1.1036x; 1.1036x over previous
#include <cuda_runtime.h>
#include <cuda_bf16.h>
#include <cstddef>
#include <cstdint>

// ---------------- problem constants ----------------
#define U_  1024
#define B_  8
#define D_  512
#define H_  8
#define HD_ 64
#define CL_ 64
#define RC_ 4
#define C_  16
#define R_  64
#define S_  16
#define M_  15
#define Q_  1104
#define KV_ 1103
#define NEG_INF_ (-100000000.0f)
#define SCALING_ 0.125f

typedef unsigned long long u64t;

// ---------------- mma / async helpers ----------------
__device__ __forceinline__ uint32_t smem_u32(const void* p) {
    uint32_t a;
    asm("{ .reg .u64 t; cvta.to.shared.u64 t, %1; cvt.u32.u64 %0, t; }" : "=r"(a) : "l"(p));
    return a;
}
#define SWZ128(o) ((o) ^ (((o) >> 3) & 0x70))

__device__ __forceinline__ void ldmx4(uint32_t* r, uint32_t addr) {
    asm volatile("ldmatrix.sync.aligned.m8n8.x4.shared.b16 {%0,%1,%2,%3}, [%4];"
                 : "=r"(r[0]), "=r"(r[1]), "=r"(r[2]), "=r"(r[3]) : "r"(addr));
}
__device__ __forceinline__ void ldmx4t(uint32_t* r, uint32_t addr) {
    asm volatile("ldmatrix.sync.aligned.m8n8.x4.trans.shared.b16 {%0,%1,%2,%3}, [%4];"
                 : "=r"(r[0]), "=r"(r[1]), "=r"(r[2]), "=r"(r[3]) : "r"(addr));
}
__device__ __forceinline__ void mma16816(float* d, const uint32_t* a,
                                         uint32_t b0, uint32_t b1) {
    asm volatile(
        "mma.sync.aligned.m16n8k16.row.col.f32.bf16.bf16.f32 "
        "{%0,%1,%2,%3}, {%4,%5,%6,%7}, {%8,%9}, {%0,%1,%2,%3};"
        : "+f"(d[0]), "+f"(d[1]), "+f"(d[2]), "+f"(d[3])
        : "r"(a[0]), "r"(a[1]), "r"(a[2]), "r"(a[3]), "r"(b0), "r"(b1));
}
__device__ __forceinline__ void cpa16(uint32_t dst, const void* src) {
    asm volatile("cp.async.cg.shared.global [%0], [%1], 16;" :: "r"(dst), "l"(src));
}
#define CPA_COMMIT() asm volatile("cp.async.commit_group;" ::: "memory")
#define CPA_WAIT1()  asm volatile("cp.async.wait_group 1;" ::: "memory")
#define CPA_WAIT0()  asm volatile("cp.async.wait_group 0;" ::: "memory")

// pack two floats into bf16x2 hi and lo words
__device__ __forceinline__ void pack_hl(float x, float y, uint32_t& hi, uint32_t& lo) {
    __nv_bfloat16 h0 = __float2bfloat16(x), h1 = __float2bfloat16(y);
    __nv_bfloat16 l0 = __float2bfloat16(x - __bfloat162float(h0));
    __nv_bfloat16 l1 = __float2bfloat16(y - __bfloat162float(h1));
    hi = (uint32_t)__bfloat16_as_ushort(h0) | ((uint32_t)__bfloat16_as_ushort(h1) << 16);
    lo = (uint32_t)__bfloat16_as_ushort(l0) | ((uint32_t)__bfloat16_as_ushort(l1) << 16);
}

// ---------------- scratch (device globals; no allocs) ----------------
__device__ float g_pos[(size_t)192 * D_];
__device__ float g_attn[(size_t)Q_ * B_ * D_];
__device__ float g_ps[(size_t)64 * 1024 * 192];     // (q+pbv).pos^T band (dvp folded)
__device__ float g_dvp[8 * 192];                    // (pbv-pbu).pos per head
// weights: W_q 0..511 | W_kv 512..1535 | W_out 1536..2047 | W_pos 2048..2559
__device__ __nv_bfloat16 g_whi[(size_t)2560 * 512];
__device__ __nv_bfloat16 g_wlo[(size_t)2560 * 512];
// A concat: [mem|rc|utt|summ|pos]; rows 0..8703 overwritten by attention output
__device__ __nv_bfloat16 g_ahi[(size_t)9216 * 512];
__device__ __nv_bfloat16 g_alo[(size_t)9216 * 512];
__device__ __nv_bfloat16 g_poshi[(size_t)192 * 512];
__device__ __nv_bfloat16 g_poslo[(size_t)192 * 512];
// q (with pbu+bias folded) and kv as bf16 hi/lo (no fp32 copies)
__device__ __nv_bfloat16 g_qhi[(size_t)Q_ * B_ * 512];
__device__ __nv_bfloat16 g_qlo[(size_t)Q_ * B_ * 512];
__device__ __nv_bfloat16 g_kvhi[(size_t)KV_ * B_ * 1024];
__device__ __nv_bfloat16 g_kvlo[(size_t)KV_ * B_ * 1024];

__device__ __forceinline__ int kv_row_of(int i, int c, int ustart) {
    return (i < c) ? i
         : (i < c + 4 ? M_ + c * 4 + (i - c)
                      : M_ + R_ + ustart + (i - c - 4));
}

// =====================================================================
// All-weights split
// =====================================================================
__global__ void conv_w_all(const float* __restrict__ Wq, const float* __restrict__ Wkv,
                           const float* __restrict__ Wout, const float* __restrict__ Wpos)
{
    int i = blockIdx.x * 256 + threadIdx.x;
    int row = i >> 9, col = i & 511;
    const float* src; int lr;
    if (row < 512)       { src = Wq;   lr = row; }
    else if (row < 1536) { src = Wkv;  lr = row - 512; }
    else if (row < 2048) { src = Wout; lr = row - 1536; }
    else                 { src = Wpos; lr = row - 2048; }
    float a = src[(size_t)lr * 512 + col];
    __nv_bfloat16 h = __float2bfloat16(a);
    g_whi[i] = h;
    g_wlo[i] = __float2bfloat16(a - __bfloat162float(h));
}

// =====================================================================
// A split (concat of <=4 row segments)
// =====================================================================
__global__ void conv_a_kernel(const float* __restrict__ A0, const float* __restrict__ A1,
                              const float* __restrict__ A2, const float* __restrict__ A3,
                              int r1, int r2, int r3, int nrows, int dst_row0)
{
    int i = blockIdx.x * 256 + threadIdx.x;
    if (i >= nrows * 128) return;
    int row = i >> 7, c4 = (i & 127) * 4;
    const float* src; int lr;
    if (row < r1)      { src = A0; lr = row; }
    else if (row < r2) { src = A1; lr = row - r1; }
    else if (row < r3) { src = A2; lr = row - r2; }
    else               { src = A3; lr = row - r3; }
    float4 v = *(const float4*)(src + (size_t)lr * 512 + c4);
    uint32_t h0, l0, h1, l1;
    pack_hl(v.x, v.y, h0, l0);
    pack_hl(v.z, v.w, h1, l1);
    size_t o = (size_t)(dst_row0 + row) * 512 + c4;
    *(uint2*)&g_ahi[o] = make_uint2(h0, h1);
    *(uint2*)&g_alo[o] = make_uint2(l0, l1);
}

// =====================================================================
// pos split: g_pos (192x512 fp32; row 191 zero) -> g_poshi/g_poslo
// =====================================================================
__global__ void conv_pos_kernel()
{
    int i = blockIdx.x * 256 + threadIdx.x;
    if (i >= 192 * 256) return;
    int row = i >> 8, c2 = (i & 255) * 2;
    float2 v = *(const float2*)(g_pos + (size_t)row * 512 + c2);
    uint32_t hi, lo;
    pack_hl(v.x, v.y, hi, lo);
    *(uint32_t*)&g_poshi[(size_t)row * 512 + c2] = hi;
    *(uint32_t*)&g_poslo[(size_t)row * 512 + c2] = lo;
}

// =====================================================================
// dvp kernel: g_dvp[h][pl] = (pbv[h]-pbu[h]).pos[pl]  (fp32 exact)
// =====================================================================
__global__ void dvp_kernel(const float* __restrict__ pbu, const float* __restrict__ pbv)
{
    const int h = blockIdx.x;
    int pl = threadIdx.x;
    if (pl >= 192) return;
    float s = 0.f;
    const float4* pp = (const float4*)(g_pos + (size_t)pl * 512 + h * 64);
    const float4* up = (const float4*)(pbu + h * 64);
    const float4* vp = (const float4*)(pbv + h * 64);
    #pragma unroll 4
    for (int k4 = 0; k4 < 16; k4++) {
        float4 a = pp[k4], uu = up[k4], vv = vp[k4];
        s += a.x * (vv.x - uu.x) + a.y * (vv.y - uu.y)
           + a.z * (vv.z - uu.z) + a.w * (vv.w - uu.w);
    }
    g_dvp[h * 192 + pl] = s;
}

// =====================================================================
// GEMM mainloop: 128x128 tile, cp.async 3-stage, 24 chunks
// =====================================================================
#define GSM_TOTAL 98304

#define GEMM_MAINLOOP(AHI, ALO, WHI, WLO, MRTOT)                                    \
    float acc[2][8][4] = {};                                                        \
    {                                                                               \
        auto issue = [&](int cc) {                                                  \
            const int seg = cc >> 3;                                                \
            const int k0 = (cc & 7) * 64;                                           \
            const __nv_bfloat16* asrc = (seg == 1) ? (ALO) : (AHI);                 \
            const __nv_bfloat16* wsrc = (seg == 2) ? (WLO) : (WHI);                 \
            char* abuf = gsm + (cc % 3) * 16384;                                    \
            char* bbuf = gsm + 49152 + (cc % 3) * 16384;                            \
            _Pragma("unroll")                                                       \
            for (int t = 0; t < 4; t++) {                                           \
                int ar = car + t * 32;                                              \
                int gr = row0 + ar; if (gr >= (MRTOT)) gr = (MRTOT) - 1;            \
                cpa16(smem_u32(abuf) + SWZ128((uint32_t)(ar * 128 + cg8 * 16)),     \
                      asrc + (size_t)gr * 512 + k0 + cg8 * 8);                      \
            }                                                                       \
            _Pragma("unroll")                                                       \
            for (int t = 0; t < 4; t++) {                                           \
                int br = car + t * 32;                                              \
                cpa16(smem_u32(bbuf) + SWZ128((uint32_t)(br * 128 + cg8 * 16)),     \
                      wsrc + (size_t)(col0 + br) * 512 + k0 + cg8 * 8);             \
            }                                                                       \
            CPA_COMMIT();                                                           \
        };                                                                          \
        issue(0);                                                                   \
        issue(1);                                                                   \
        const int l15 = lane & 15, lh = lane >> 4;                                  \
        const int l8 = lane & 7, lg = lane >> 3;                                    \
        for (int cc = 0; cc < 24; cc++) {                                           \
            if (cc < 23) CPA_WAIT1(); else CPA_WAIT0();                             \
            __syncthreads();                                                        \
            const uint32_t Ab = sb + (cc % 3) * 16384;                              \
            const uint32_t Bb = sb + 49152 + (cc % 3) * 16384;                      \
            _Pragma("unroll")                                                       \
            for (int s = 0; s < 4; s++) {                                           \
                uint32_t afr[2][4];                                                 \
                _Pragma("unroll")                                                   \
                for (int mt = 0; mt < 2; mt++) {                                    \
                    int r = wm * 32 + mt * 16 + l15;                                \
                    ldmx4(afr[mt], Ab + SWZ128((uint32_t)(r * 128 + s * 32 + lh * 16))); \
                }                                                                   \
                uint32_t bfr[4][4];                                                 \
                _Pragma("unroll")                                                   \
                for (int bt = 0; bt < 4; bt++) {                                    \
                    int n = wn * 64 + bt * 16 + ((lg >> 1) ? 8 : 0) + l8;           \
                    ldmx4(bfr[bt], Bb + SWZ128((uint32_t)(n * 128 + s * 32 + (lg & 1) * 16))); \
                }                                                                   \
                _Pragma("unroll")                                                   \
                for (int mt = 0; mt < 2; mt++)                                      \
                    _Pragma("unroll")                                               \
                    for (int nt = 0; nt < 8; nt++) {                                \
                        int bt = nt >> 1, sub = nt & 1;                             \
                        mma16816(acc[mt][nt], afr[mt], bfr[bt][2*sub], bfr[bt][2*sub+1]); \
                    }                                                               \
            }                                                                       \
            if (cc + 2 < 24) issue(cc + 2);                                         \
        }                                                                           \
    }

// ---- generic GEMM (pos / out projections), fp32 out ----
__global__ __launch_bounds__(256, 2) void gemm_tc_kernel(
    const __nv_bfloat16* __restrict__ Ahi, const __nv_bfloat16* __restrict__ Alo,
    const __nv_bfloat16* __restrict__ Whib, const __nv_bfloat16* __restrict__ Wlob,
    float* __restrict__ Cm, int Mr, int ldc, const float* __restrict__ bias)
{
    extern __shared__ char gsm[];
    const uint32_t sb = smem_u32(gsm);
    const int tid = threadIdx.x;
    const int wid = tid >> 5, lane = tid & 31;
    const int wm = wid & 3, wn = wid >> 2;
    const int row0 = blockIdx.y * 128, col0 = blockIdx.x * 128;
    const int car = tid >> 3, cg8 = tid & 7;

    GEMM_MAINLOOP(Ahi, Alo, Whib, Wlob, Mr)

    const int quad = lane >> 2, tq = lane & 3;
    #pragma unroll
    for (int mt = 0; mt < 2; mt++) {
        #pragma unroll
        for (int nt = 0; nt < 8; nt++) {
            int gr0 = row0 + wm * 32 + mt * 16 + quad;
            int gc  = col0 + wn * 64 + nt * 8 + tq * 2;
            float b0 = bias ? bias[gc]     : 0.f;
            float b1 = bias ? bias[gc + 1] : 0.f;
            #pragma unroll
            for (int half = 0; half < 2; half++) {
                int gr = gr0 + half * 8;
                if (gr < Mr) {
                    float2 v = {acc[mt][nt][half*2+0] + b0, acc[mt][nt][half*2+1] + b1};
                    *(float2*)&Cm[(size_t)gr * ldc + gc] = v;
                }
            }
        }
    }
}

// ---- fused Q+KV GEMM: writes q (+b_q+pbu) and kv (+b_kv) as bf16 hi/lo ----
__global__ __launch_bounds__(256, 2) void gemm_qkv_kernel(
    const float* __restrict__ b_q, const float* __restrict__ b_kv,
    const float* __restrict__ pbu)
{
    extern __shared__ char gsm[];
    const uint32_t sb = smem_u32(gsm);
    const int tid = threadIdx.x;
    const int wid = tid >> 5, lane = tid & 31;
    const int wm = wid & 3, wn = wid >> 2;
    const int row0 = blockIdx.y * 128, col0 = blockIdx.x * 128;
    const int car = tid >> 3, cg8 = tid & 7;

    GEMM_MAINLOOP(g_ahi, g_alo, g_whi, g_wlo, 8952)

    const int quad = lane >> 2, tq = lane & 3;
    const bool is_q = (col0 < 512);
    #pragma unroll
    for (int mt = 0; mt < 2; mt++) {
        #pragma unroll
        for (int nt = 0; nt < 8; nt++) {
            int gr0 = row0 + wm * 32 + mt * 16 + quad;
            int gc  = col0 + wn * 64 + nt * 8 + tq * 2;
            #pragma unroll
            for (int half = 0; half < 2; half++) {
                int gr = gr0 + half * 8;
                if (gr >= 8952) continue;
                float2 v = {acc[mt][nt][half*2+0], acc[mt][nt][half*2+1]};
                if (is_q) {
                    int qr = gr - 120;
                    if (qr >= 0) {
                        v.x += b_q[gc] + pbu[gc];
                        v.y += b_q[gc + 1] + pbu[gc + 1];
                        uint32_t hi, lo;
                        pack_hl(v.x, v.y, hi, lo);
                        *(uint32_t*)&g_qhi[(size_t)qr * 512 + gc] = hi;
                        *(uint32_t*)&g_qlo[(size_t)qr * 512 + gc] = lo;
                    }
                } else {
                    int kc = gc - 512;
                    if (gr < 8824) {
                        v.x += b_kv[kc]; v.y += b_kv[kc + 1];
                        uint32_t hi, lo;
                        pack_hl(v.x, v.y, hi, lo);
                        *(uint32_t*)&g_kvhi[(size_t)gr * 1024 + kc] = hi;
                        *(uint32_t*)&g_kvlo[(size_t)gr * 1024 + kc] = lo;
                    }
                }
            }
        }
    }
}

// =====================================================================
// ps kernel: g_ps[bh][u][pl] = (q+pbu).pos^T + dvp[h][pl] via HMMA.
// grid (16 u-tiles of 64, 64 bh), 256 threads, 64KB smem -> 2 CTA/SM.
// smem: QHI 0 (64x128B), QLO 8192, PH 16384 (192x128B), PL 40960
// =====================================================================
#define PS_TOTAL 65536

__global__ __launch_bounds__(256) void ps_kernel()
{
    extern __shared__ char psm[];
    const uint32_t sb = smem_u32(psm);
    const int ut = blockIdx.x, bh = blockIdx.y;
    const int b = bh >> 3, h = bh & 7;
    const int tid = threadIdx.x;
    const int wid = tid >> 5, lane = tid & 31;

    // cp.async pos rows (192, hi/lo) + Q rows (64, hi/lo)
    for (int idx = tid; idx < 192 * 8; idx += 256) {
        int r = idx >> 3, ch = idx & 7;
        size_t go = (size_t)r * 512 + h * 64 + ch * 8;
        uint32_t so = SWZ128((uint32_t)(r * 128 + ch * 16));
        cpa16(sb + 16384 + so, g_poshi + go);
        cpa16(sb + 40960 + so, g_poslo + go);
    }
    for (int idx = tid; idx < 64 * 8; idx += 256) {
        int r = idx >> 3, ch = idx & 7;
        int qrow = R_ + ut * 64 + r;
        size_t go = ((size_t)qrow * B_ + b) * 512 + h * 64 + ch * 8;
        uint32_t so = SWZ128((uint32_t)(r * 128 + ch * 16));
        cpa16(sb + so, g_qhi + go);
        cpa16(sb + 8192 + so, g_qlo + go);
    }
    CPA_COMMIT();
    CPA_WAIT0();
    __syncthreads();

    const int wm = wid >> 2, wn = wid & 3;
    const int l15 = lane & 15, lh = lane >> 4;
    const int l8 = lane & 7, lg = lane >> 3;
    const int quad = lane >> 2, tq = lane & 3;

    float acc[2][3][2][4] = {};
    #pragma unroll
    for (int pass = 0; pass < 3; pass++) {
        const uint32_t Ab = sb + ((pass == 1) ? 8192 : 0);
        const uint32_t Bb = sb + ((pass == 2) ? 40960 : 16384);
        #pragma unroll
        for (int s = 0; s < 4; s++) {
            uint32_t afr[2][4];
            #pragma unroll
            for (int mi = 0; mi < 2; mi++) {
                int r = (wm * 2 + mi) * 16 + l15;
                ldmx4(afr[mi], Ab + SWZ128((uint32_t)(r * 128 + s * 32 + lh * 16)));
            }
            #pragma unroll
            for (int nj = 0; nj < 3; nj++) {
                uint32_t bfr[4];
                int n = (wn + 4 * nj) * 16 + ((lg >> 1) ? 8 : 0) + l8;
                ldmx4(bfr, Bb + SWZ128((uint32_t)(n * 128 + s * 32 + (lg & 1) * 16)));
                #pragma unroll
                for (int mi = 0; mi < 2; mi++) {
                    mma16816(acc[mi][nj][0], afr[mi], bfr[0], bfr[1]);
                    mma16816(acc[mi][nj][1], afr[mi], bfr[2], bfr[3]);
                }
            }
        }
    }
    // epilogue -> g_ps (+dvp correction)
    #pragma unroll
    for (int mi = 0; mi < 2; mi++) {
        #pragma unroll
        for (int nj = 0; nj < 3; nj++) {
            #pragma unroll
            for (int nh = 0; nh < 2; nh++) {
                int col = (wn + 4 * nj) * 16 + nh * 8 + tq * 2;
                float2 dv = *(const float2*)&g_dvp[h * 192 + col];
                #pragma unroll
                for (int hf = 0; hf < 2; hf++) {
                    int r = (wm * 2 + mi) * 16 + quad + hf * 8;
                    int u = ut * 64 + r;
                    *(float2*)&g_ps[((size_t)bh * 1024 + u) * 192 + col] =
                        make_float2(acc[mi][nj][nh][hf * 2 + 0] + dv.x,
                                    acc[mi][nj][nh][hf * 2 + 1] + dv.y);
                }
            }
        }
    }
}

// =====================================================================
// Fused attention v7: all operands via cp.async (no scalar conversion).
// 512 threads, 113280B smem -> 2 CTAs/SM.
// smem: QHI 0 (10240) QLO 10240 | KHI 20480 KLO 40960 (V reuses)
//       SS 61440 (fp32 stride 648B, 80 rows) ; P overlays: PHI 61440, PLO 84624
// =====================================================================
#define FZ_QHI 0
#define FZ_QLO 10240
#define FZ_KHI 20480
#define FZ_KLO 40960
#define FZ_SS  61440
#define FZ_PHI 61440
#define FZ_PLO 84624
#define FZ_TOTAL 113280

__global__ __launch_bounds__(512, 2) void fused_attn_kernel(
    const int* __restrict__ lengths)
{
    extern __shared__ char fsm[];
    const uint32_t sb = smem_u32(fsm);

    const int c = blockIdx.x, bh = blockIdx.y;
    const int b = bh >> 3, h = bh & 7;
    const int tid = threadIdx.x;
    const int wid = tid >> 5, lane = tid & 31;
    const int ustart = (c == 0) ? 0 : (c - 1) * CL_;
    const int ncols = c + 4 + ((c == 0) ? 64 : 128);
    const int len_b = lengths[b];
    const int pbase = (c == 0) ? 127 : 63;

    // ---- cp.async Q (69 rows, hi/lo; pad rows stale -> outputs never stored) ----
    for (int idx = tid; idx < 69 * 8; idx += 512) {
        int r = idx >> 3, ch = idx & 7;
        int qrow = (r < 4) ? c * 4 + r
                 : (r < 68 ? R_ + c * 64 + (r - 4) : R_ + U_ + c);
        size_t go = ((size_t)qrow * B_ + b) * 512 + h * 64 + ch * 8;
        uint32_t so = SWZ128((uint32_t)(r * 128 + ch * 16));
        cpa16(sb + FZ_QHI + so, g_qhi + go);
        cpa16(sb + FZ_QLO + so, g_qlo + go);
    }
    // ---- cp.async K (ncols rows; pad cols masked in softmax) ----
    for (int idx = tid; idx < ncols * 8; idx += 512) {
        int r = idx >> 3, ch = idx & 7;
        int kvrow = kv_row_of(r, c, ustart);
        size_t go = ((size_t)kvrow * B_ + b) * 1024 + h * 64 + ch * 8;
        uint32_t so = SWZ128((uint32_t)(r * 128 + ch * 16));
        cpa16(sb + FZ_KHI + so, g_kvhi + go);
        cpa16(sb + FZ_KLO + so, g_kvlo + go);
    }
    CPA_COMMIT();
    CPA_WAIT0();
    __syncthreads();

    const int l15 = lane & 15, lh = lane >> 4;
    const int l8 = lane & 7, lg = lane >> 3;
    const int quad = lane >> 2, tq = lane & 3;
    const int wmc = wid / 3, wnc = wid % 3;   // wid 15 -> wmc 5 inactive

    // ---- C1: scores = (Q+pbu).K^T (HMMA, 3 passes) ----
    if (wmc < 5) {
        float acc[4][2][4] = {};
        #pragma unroll
        for (int pass = 0; pass < 3; pass++) {
            const uint32_t Ab = sb + ((pass == 1) ? FZ_QLO : FZ_QHI);
            const uint32_t Bb = sb + ((pass == 2) ? FZ_KLO : FZ_KHI);
            #pragma unroll
            for (int s = 0; s < 4; s++) {
                uint32_t afr[4];
                ldmx4(afr, Ab + SWZ128((uint32_t)((wmc * 16 + l15) * 128 + s * 32 + lh * 16)));
                #pragma unroll
                for (int nj = 0; nj < 4; nj++) {
                    int nt = wnc + 3 * nj;
                    if (nt < 10) {
                        uint32_t bfr[4];
                        int n = nt * 16 + ((lg >> 1) ? 8 : 0) + l8;
                        ldmx4(bfr, Bb + SWZ128((uint32_t)(n * 128 + s * 32 + (lg & 1) * 16)));
                        mma16816(acc[nj][0], afr, bfr[0], bfr[1]);
                        mma16816(acc[nj][1], afr, bfr[2], bfr[3]);
                    }
                }
            }
        }
        #pragma unroll
        for (int nj = 0; nj < 4; nj++) {
            int nt = wnc + 3 * nj;
            if (nt < 10) {
                int r0 = wmc * 16 + quad;
                #pragma unroll
                for (int hf = 0; hf < 2; hf++) {
                    int col = nt * 16 + hf * 8 + tq * 2;
                    *(float2*)(fsm + FZ_SS + (size_t)r0 * 648 + col * 4) =
                        make_float2(acc[nj][hf][0], acc[nj][hf][1]);
                    *(float2*)(fsm + FZ_SS + (size_t)(r0 + 8) * 648 + col * 4) =
                        make_float2(acc[nj][hf][2], acc[nj][hf][3]);
                }
            }
        }
    }
    __syncthreads();

    // ---- V load via cp.async (overwrites K region) + zero pad rows ----
    {
        uint4 z = make_uint4(0, 0, 0, 0);
        for (int idx = tid; idx < (160 - ncols) * 8; idx += 512) {
            int r = ncols + (idx >> 3), ch = idx & 7;
            uint32_t so = SWZ128((uint32_t)(r * 128 + ch * 16));
            *(uint4*)(fsm + FZ_KHI + so) = z;
            *(uint4*)(fsm + FZ_KLO + so) = z;
        }
        for (int idx = tid; idx < ncols * 8; idx += 512) {
            int r = idx >> 3, ch = idx & 7;
            int kvrow = kv_row_of(r, c, ustart);
            size_t go = ((size_t)kvrow * B_ + b) * 1024 + 512 + h * 64 + ch * 8;
            uint32_t so = SWZ128((uint32_t)(r * 128 + ch * 16));
            cpa16(sb + FZ_KHI + so, g_kvhi + go);
            cpa16(sb + FZ_KLO + so, g_kvlo + go);
        }
        CPA_COMMIT();
    }

    // ---- softmax phase A (reads scores + g_ps band) ----
    float pvals[5][5];
    {
        const int limit_j = len_b - ustart;
        const int uc0 = c + 4;
        int slot = 0;
        for (int r = wid; r < 69; r += 16, slot++) {
            const bool is_utt = (r >= 4) && (r < 68);
            const int u_loc = r - 4;
            const float* psrow = g_ps + ((size_t)bh * 1024 + c * 64 + u_loc) * 192;
            const int plb = pbase - u_loc - uc0;
            float vals[5];
            float mx = -3.4e38f;
            #pragma unroll
            for (int g = 0; g < 5; g++) {
                int i = lane + 32 * g;
                float v = -3.4e38f;
                if (i < ncols) {
                    float s = *(const float*)(fsm + FZ_SS + (size_t)r * 648 + i * 4);
                    if (i >= uc0) {
                        int j = i - uc0;
                        if (is_utt) s += psrow[plb + i];
                        v = (j >= limit_j) ? NEG_INF_ : s * SCALING_;
                    } else {
                        v = s * SCALING_;
                    }
                }
                vals[g] = v;
                mx = fmaxf(mx, v);
            }
            #pragma unroll
            for (int o = 16; o > 0; o >>= 1) mx = fmaxf(mx, __shfl_xor_sync(~0u, mx, o));
            float sum = 0.f;
            #pragma unroll
            for (int g = 0; g < 5; g++) {
                float e = __expf(vals[g] - mx);
                vals[g] = e;
                sum += e;
            }
            #pragma unroll
            for (int o = 16; o > 0; o >>= 1) sum += __shfl_xor_sync(~0u, sum, o);
            float inv = 1.f / sum;
            #pragma unroll
            for (int g = 0; g < 5; g++) pvals[slot][g] = vals[g] * inv;
        }
    }
    __syncthreads();

    // ---- phase B: write P bf16 hi/lo over dead score region ----
    {
        int slot = 0;
        for (int r = wid; r < 69; r += 16, slot++) {
            #pragma unroll
            for (int g = 0; g < 5; g++) {
                int i = lane + 32 * g;
                float p = (i < ncols) ? pvals[slot][g] : 0.f;
                __nv_bfloat16 hp = __float2bfloat16(p);
                __nv_bfloat16 lp = __float2bfloat16(p - __bfloat162float(hp));
                *(ushort*)(fsm + FZ_PHI + r * 336 + i * 2) = __bfloat16_as_ushort(hp);
                *(ushort*)(fsm + FZ_PLO + r * 336 + i * 2) = __bfloat16_as_ushort(lp);
            }
        }
    }
    CPA_WAIT0();
    __syncthreads();

    // ---- PV: out = P.V (HMMA, 3 passes) ----
    {
        const int wmp = wid >> 2, wnp = wid & 3;
        float accp[2][2][4] = {};
        #pragma unroll
        for (int pass = 0; pass < 3; pass++) {
            const uint32_t Ab = sb + ((pass == 1) ? FZ_PLO : FZ_PHI);
            const uint32_t Bb = sb + ((pass == 2) ? FZ_KLO : FZ_KHI);
            #pragma unroll
            for (int kk = 0; kk < 10; kk++) {
                uint32_t bfr[4];
                ldmx4t(bfr, Bb + SWZ128((uint32_t)((kk * 16 + l15) * 128 + wnp * 32 + lh * 16)));
                #pragma unroll
                for (int mi = 0; mi < 2; mi++) {
                    int m = wmp + 4 * mi;
                    if (m < 5) {
                        uint32_t afr[4];
                        ldmx4(afr, Ab + (uint32_t)((m * 16 + l15) * 336 + kk * 32 + lh * 16));
                        mma16816(accp[mi][0], afr, bfr[0], bfr[1]);
                        mma16816(accp[mi][1], afr, bfr[2], bfr[3]);
                    }
                }
            }
        }
        #pragma unroll
        for (int mi = 0; mi < 2; mi++) {
            int m = wmp + 4 * mi;
            if (m >= 5) continue;
            int r0 = m * 16 + quad;
            #pragma unroll
            for (int hf = 0; hf < 2; hf++) {
                int r = r0 + hf * 8;
                if (r < 68) {
                    int qrow = (r < 4) ? c * 4 + r : R_ + c * 64 + (r - 4);
                    size_t base = ((size_t)qrow * B_ + b) * 512 + h * 64;
                    #pragma unroll
                    for (int n = 0; n < 2; n++) {
                        int d = wnp * 16 + n * 8 + tq * 2;
                        uint32_t vhi, vlo;
                        pack_hl(accp[mi][n][hf*2+0], accp[mi][n][hf*2+1], vhi, vlo);
                        *(uint32_t*)&g_ahi[base + d] = vhi;
                        *(uint32_t*)&g_alo[base + d] = vlo;
                    }
                } else if (r == 68) {
                    int qrow = R_ + U_ + c;
                    float* dst = g_attn + ((size_t)qrow * B_ + b) * 512 + h * 64;
                    #pragma unroll
                    for (int n = 0; n < 2; n++) {
                        int d = wnp * 16 + n * 8 + tq * 2;
                        *(float2*)(dst + d) =
                            make_float2(accp[mi][n][hf*2+0], accp[mi][n][hf*2+1]);
                    }
                }
            }
        }
    }
}

// ---------------- out_mem = clip(attn[R+U:], -10, 10) ----------------
__global__ void clip_kernel(float* __restrict__ out)
{
    const size_t off = (size_t)(R_ + U_) * B_ * D_;
    int i = blockIdx.x * 256 + threadIdx.x;
    float v = g_attn[off + i];
    out[off + i] = fminf(10.f, fmaxf(-10.f, v));
}

// ---------------- launch ----------------
extern "C" void kernel_launch(void* const* d_in, const int* in_sizes, int n_in,
                              void* d_out, int out_size)
{
    const float* utt    = (const float*)d_in[0];
    const int*   lens   = (const int*)  d_in[1];
    const float* rc     = (const float*)d_in[2];
    const float* summ   = (const float*)d_in[3];
    const float* mem    = (const float*)d_in[4];
    const float* pos_e  = (const float*)d_in[6];
    const float* W_kv   = (const float*)d_in[7];
    const float* b_kv   = (const float*)d_in[8];
    const float* W_q    = (const float*)d_in[9];
    const float* b_q    = (const float*)d_in[10];
    const float* W_out  = (const float*)d_in[11];
    const float* b_out  = (const float*)d_in[12];
    const float* W_pos  = (const float*)d_in[13];
    const float* pbu    = (const float*)d_in[14];
    const float* pbv    = (const float*)d_in[15];
    float* out = (float*)d_out;

    float *pos_buf;
    __nv_bfloat16 *ahi, *alo, *whi, *wlo;
    cudaGetSymbolAddress((void**)&pos_buf, g_pos);
    cudaGetSymbolAddress((void**)&ahi,     g_ahi);
    cudaGetSymbolAddress((void**)&alo,     g_alo);
    cudaGetSymbolAddress((void**)&whi,     g_whi);
    cudaGetSymbolAddress((void**)&wlo,     g_wlo);

    cudaFuncSetAttribute(fused_attn_kernel,
                         cudaFuncAttributeMaxDynamicSharedMemorySize, FZ_TOTAL);
    cudaFuncSetAttribute(ps_kernel,
                         cudaFuncAttributeMaxDynamicSharedMemorySize, PS_TOTAL);
    cudaFuncSetAttribute(gemm_tc_kernel,
                         cudaFuncAttributeMaxDynamicSharedMemorySize, GSM_TOTAL);
    cudaFuncSetAttribute(gemm_qkv_kernel,
                         cudaFuncAttributeMaxDynamicSharedMemorySize, GSM_TOTAL);

    const dim3 blk(256);
    const float* pos_src = pos_e + (size_t)(U_ - 128) * D_;

    // ---- conversions ----
    conv_a_kernel<<<dim3((8952 * 128 + 255) / 256), blk>>>(
        mem, rc, utt, summ, 120, 632, 8824, 8952, 0);
    conv_a_kernel<<<dim3((191 * 128 + 255) / 256), blk>>>(
        pos_src, pos_src, pos_src, pos_src, 191, 191, 191, 191, 8952);
    conv_w_all<<<dim3(2560 * 512 / 256), blk>>>(W_q, W_kv, W_out, W_pos);

    // ---- fused Q+KV projection (bf16 hi/lo out; pbu folded into Q) ----
    gemm_qkv_kernel<<<dim3(12, 70), blk, GSM_TOTAL>>>(b_q, b_kv, pbu);

    // ---- pos projection -> fp32 -> bf16 split; dvp correction ----
    gemm_tc_kernel<<<dim3(4, 2), blk, GSM_TOTAL>>>(
        ahi + (size_t)8952 * 512, alo + (size_t)8952 * 512,
        whi + (size_t)2048 * 512, wlo + (size_t)2048 * 512,
        pos_buf, 191, D_, nullptr);
    conv_pos_kernel<<<dim3(192), blk>>>();
    dvp_kernel<<<dim3(8), blk>>>(pbu, pbv);

    // ---- posS band then fused attention ----
    ps_kernel<<<dim3(16, 64), blk, PS_TOTAL>>>();
    fused_attn_kernel<<<dim3(C_, 64), dim3(512), FZ_TOTAL>>>(lens);

    // ---- output projection ----
    gemm_tc_kernel<<<dim3(4, 68), blk, GSM_TOTAL>>>(
        ahi, alo, whi + (size_t)1536 * 512, wlo + (size_t)1536 * 512,
        out, (R_ + U_) * B_, D_, b_out);
    clip_kernel<<<dim3(256), blk>>>(out);
}

// round 15
// speedup vs baseline: 1.2026x; 1.0897x over previous
#include <cuda_runtime.h>
#include <cuda_bf16.h>
#include <cstddef>
#include <cstdint>

// ---------------- problem constants ----------------
#define U_  1024
#define B_  8
#define D_  512
#define H_  8
#define HD_ 64
#define CL_ 64
#define RC_ 4
#define C_  16
#define R_  64
#define S_  16
#define M_  15
#define Q_  1104
#define KV_ 1103
#define NEG_INF_ (-100000000.0f)
#define SCALING_ 0.125f

typedef unsigned long long u64t;

// ---------------- mma / async helpers ----------------
__device__ __forceinline__ uint32_t smem_u32(const void* p) {
    uint32_t a;
    asm("{ .reg .u64 t; cvta.to.shared.u64 t, %1; cvt.u32.u64 %0, t; }" : "=r"(a) : "l"(p));
    return a;
}
#define SWZ128(o) ((o) ^ (((o) >> 3) & 0x70))

__device__ __forceinline__ void ldmx4(uint32_t* r, uint32_t addr) {
    asm volatile("ldmatrix.sync.aligned.m8n8.x4.shared.b16 {%0,%1,%2,%3}, [%4];"
                 : "=r"(r[0]), "=r"(r[1]), "=r"(r[2]), "=r"(r[3]) : "r"(addr));
}
__device__ __forceinline__ void ldmx4t(uint32_t* r, uint32_t addr) {
    asm volatile("ldmatrix.sync.aligned.m8n8.x4.trans.shared.b16 {%0,%1,%2,%3}, [%4];"
                 : "=r"(r[0]), "=r"(r[1]), "=r"(r[2]), "=r"(r[3]) : "r"(addr));
}
__device__ __forceinline__ void mma16816(float* d, const uint32_t* a,
                                         uint32_t b0, uint32_t b1) {
    asm volatile(
        "mma.sync.aligned.m16n8k16.row.col.f32.bf16.bf16.f32 "
        "{%0,%1,%2,%3}, {%4,%5,%6,%7}, {%8,%9}, {%0,%1,%2,%3};"
        : "+f"(d[0]), "+f"(d[1]), "+f"(d[2]), "+f"(d[3])
        : "r"(a[0]), "r"(a[1]), "r"(a[2]), "r"(a[3]), "r"(b0), "r"(b1));
}
__device__ __forceinline__ void cpa16(uint32_t dst, const void* src) {
    asm volatile("cp.async.cg.shared.global [%0], [%1], 16;" :: "r"(dst), "l"(src));
}
#define CPA_COMMIT() asm volatile("cp.async.commit_group;" ::: "memory")
#define CPA_WAIT1()  asm volatile("cp.async.wait_group 1;" ::: "memory")
#define CPA_WAIT0()  asm volatile("cp.async.wait_group 0;" ::: "memory")

// pack two floats into bf16x2 hi and lo words
__device__ __forceinline__ void pack_hl(float x, float y, uint32_t& hi, uint32_t& lo) {
    __nv_bfloat16 h0 = __float2bfloat16(x), h1 = __float2bfloat16(y);
    __nv_bfloat16 l0 = __float2bfloat16(x - __bfloat162float(h0));
    __nv_bfloat16 l1 = __float2bfloat16(y - __bfloat162float(h1));
    hi = (uint32_t)__bfloat16_as_ushort(h0) | ((uint32_t)__bfloat16_as_ushort(h1) << 16);
    lo = (uint32_t)__bfloat16_as_ushort(l0) | ((uint32_t)__bfloat16_as_ushort(l1) << 16);
}

// ---------------- scratch (device globals; no allocs) ----------------
__device__ float g_pos[(size_t)256 * D_];           // fp32 pos (rows >=191 zero)
__device__ float g_ps[(size_t)64 * 1024 * 192];     // (q+pbv).pos^T band (dvp folded)
__device__ float g_dvp[8 * 192];                    // (pbv-pbu).pos per head
// weights: W_q 0..511 | W_kv 512..1535 | W_out 1536..2047 | W_pos 2048..2559
__device__ __nv_bfloat16 g_whi[(size_t)2560 * 512];
__device__ __nv_bfloat16 g_wlo[(size_t)2560 * 512];
// A concat: [mem 0-119|rc 120-631|utt 632-8823|summ 8824-8951|(gap)|pos 8960-9150]
// rows 0..8703 overwritten by attention output for the out-proj
__device__ __nv_bfloat16 g_ahi[(size_t)9216 * 512];
__device__ __nv_bfloat16 g_alo[(size_t)9216 * 512];
__device__ __nv_bfloat16 g_poshi[(size_t)256 * 512];
__device__ __nv_bfloat16 g_poslo[(size_t)256 * 512];
// q (with pbu+bias folded) and kv as bf16 hi/lo (no fp32 copies)
__device__ __nv_bfloat16 g_qhi[(size_t)Q_ * B_ * 512];
__device__ __nv_bfloat16 g_qlo[(size_t)Q_ * B_ * 512];
__device__ __nv_bfloat16 g_kvhi[(size_t)KV_ * B_ * 1024];
__device__ __nv_bfloat16 g_kvlo[(size_t)KV_ * B_ * 1024];

__device__ __forceinline__ int kv_row_of(int i, int c, int ustart) {
    return (i < c) ? i
         : (i < c + 4 ? M_ + c * 4 + (i - c)
                      : M_ + R_ + ustart + (i - c - 4));
}

// =====================================================================
// All-weights split
// =====================================================================
__global__ void conv_w_all(const float* __restrict__ Wq, const float* __restrict__ Wkv,
                           const float* __restrict__ Wout, const float* __restrict__ Wpos)
{
    int i = blockIdx.x * 256 + threadIdx.x;
    int row = i >> 9, col = i & 511;
    const float* src; int lr;
    if (row < 512)       { src = Wq;   lr = row; }
    else if (row < 1536) { src = Wkv;  lr = row - 512; }
    else if (row < 2048) { src = Wout; lr = row - 1536; }
    else                 { src = Wpos; lr = row - 2048; }
    float a = src[(size_t)lr * 512 + col];
    __nv_bfloat16 h = __float2bfloat16(a);
    g_whi[i] = h;
    g_wlo[i] = __float2bfloat16(a - __bfloat162float(h));
}

// =====================================================================
// A split (concat of <=4 row segments)
// =====================================================================
__global__ void conv_a_kernel(const float* __restrict__ A0, const float* __restrict__ A1,
                              const float* __restrict__ A2, const float* __restrict__ A3,
                              int r1, int r2, int r3, int nrows, int dst_row0)
{
    int i = blockIdx.x * 256 + threadIdx.x;
    if (i >= nrows * 128) return;
    int row = i >> 7, c4 = (i & 127) * 4;
    const float* src; int lr;
    if (row < r1)      { src = A0; lr = row; }
    else if (row < r2) { src = A1; lr = row - r1; }
    else if (row < r3) { src = A2; lr = row - r2; }
    else               { src = A3; lr = row - r3; }
    float4 v = *(const float4*)(src + (size_t)lr * 512 + c4);
    uint32_t h0, l0, h1, l1;
    pack_hl(v.x, v.y, h0, l0);
    pack_hl(v.z, v.w, h1, l1);
    size_t o = (size_t)(dst_row0 + row) * 512 + c4;
    *(uint2*)&g_ahi[o] = make_uint2(h0, h1);
    *(uint2*)&g_alo[o] = make_uint2(l0, l1);
}

// =====================================================================
// dvp kernel: g_dvp[h][pl] = (pbv[h]-pbu[h]).pos[pl]  (fp32 exact)
// =====================================================================
__global__ void dvp_kernel(const float* __restrict__ pbu, const float* __restrict__ pbv)
{
    const int h = blockIdx.x;
    int pl = threadIdx.x;
    if (pl >= 192) return;
    float s = 0.f;
    if (pl < 191) {
        const float4* pp = (const float4*)(g_pos + (size_t)pl * 512 + h * 64);
        const float4* up = (const float4*)(pbu + h * 64);
        const float4* vp = (const float4*)(pbv + h * 64);
        #pragma unroll 4
        for (int k4 = 0; k4 < 16; k4++) {
            float4 a = pp[k4], uu = up[k4], vv = vp[k4];
            s += a.x * (vv.x - uu.x) + a.y * (vv.y - uu.y)
               + a.z * (vv.z - uu.z) + a.w * (vv.w - uu.w);
        }
    }
    g_dvp[h * 192 + pl] = s;
}

// =====================================================================
// GEMM mainloop: 128x128 tile, cp.async 3-stage, 24 chunks
// =====================================================================
#define GSM_TOTAL 98304

#define GEMM_MAINLOOP(AHI, ALO, WHI, WLO, MRTOT)                                    \
    float acc[2][8][4] = {};                                                        \
    {                                                                               \
        auto issue = [&](int cc) {                                                  \
            const int seg = cc >> 3;                                                \
            const int k0 = (cc & 7) * 64;                                           \
            const __nv_bfloat16* asrc = (seg == 1) ? (ALO) : (AHI);                 \
            const __nv_bfloat16* wsrc = (seg == 2) ? (WLO) : (WHI);                 \
            char* abuf = gsm + (cc % 3) * 16384;                                    \
            char* bbuf = gsm + 49152 + (cc % 3) * 16384;                            \
            _Pragma("unroll")                                                       \
            for (int t = 0; t < 4; t++) {                                           \
                int ar = car + t * 32;                                              \
                int gr = row0 + ar; if (gr >= (MRTOT)) gr = (MRTOT) - 1;            \
                cpa16(smem_u32(abuf) + SWZ128((uint32_t)(ar * 128 + cg8 * 16)),     \
                      asrc + (size_t)gr * 512 + k0 + cg8 * 8);                      \
            }                                                                       \
            _Pragma("unroll")                                                       \
            for (int t = 0; t < 4; t++) {                                           \
                int br = car + t * 32;                                              \
                cpa16(smem_u32(bbuf) + SWZ128((uint32_t)(br * 128 + cg8 * 16)),     \
                      wsrc + (size_t)(col0 + br) * 512 + k0 + cg8 * 8);             \
            }                                                                       \
            CPA_COMMIT();                                                           \
        };                                                                          \
        issue(0);                                                                   \
        issue(1);                                                                   \
        const int l15 = lane & 15, lh = lane >> 4;                                  \
        const int l8 = lane & 7, lg = lane >> 3;                                    \
        for (int cc = 0; cc < 24; cc++) {                                           \
            if (cc < 23) CPA_WAIT1(); else CPA_WAIT0();                             \
            __syncthreads();                                                        \
            const uint32_t Ab = sb + (cc % 3) * 16384;                              \
            const uint32_t Bb = sb + 49152 + (cc % 3) * 16384;                      \
            _Pragma("unroll")                                                       \
            for (int s = 0; s < 4; s++) {                                           \
                uint32_t afr[2][4];                                                 \
                _Pragma("unroll")                                                   \
                for (int mt = 0; mt < 2; mt++) {                                    \
                    int r = wm * 32 + mt * 16 + l15;                                \
                    ldmx4(afr[mt], Ab + SWZ128((uint32_t)(r * 128 + s * 32 + lh * 16))); \
                }                                                                   \
                uint32_t bfr[4][4];                                                 \
                _Pragma("unroll")                                                   \
                for (int bt = 0; bt < 4; bt++) {                                    \
                    int n = wn * 64 + bt * 16 + ((lg >> 1) ? 8 : 0) + l8;           \
                    ldmx4(bfr[bt], Bb + SWZ128((uint32_t)(n * 128 + s * 32 + (lg & 1) * 16))); \
                }                                                                   \
                _Pragma("unroll")                                                   \
                for (int mt = 0; mt < 2; mt++)                                      \
                    _Pragma("unroll")                                               \
                    for (int nt = 0; nt < 8; nt++) {                                \
                        int bt = nt >> 1, sub = nt & 1;                             \
                        mma16816(acc[mt][nt], afr[mt], bfr[bt][2*sub], bfr[bt][2*sub+1]); \
                    }                                                               \
            }                                                                       \
            if (cc + 2 < 24) issue(cc + 2);                                         \
        }                                                                           \
    }

// ---- generic GEMM (out projection), fp32 out ----
__global__ __launch_bounds__(256, 2) void gemm_tc_kernel(
    const __nv_bfloat16* __restrict__ Ahi, const __nv_bfloat16* __restrict__ Alo,
    const __nv_bfloat16* __restrict__ Whib, const __nv_bfloat16* __restrict__ Wlob,
    float* __restrict__ Cm, int Mr, int ldc, const float* __restrict__ bias)
{
    extern __shared__ char gsm[];
    const uint32_t sb = smem_u32(gsm);
    const int tid = threadIdx.x;
    const int wid = tid >> 5, lane = tid & 31;
    const int wm = wid & 3, wn = wid >> 2;
    const int row0 = blockIdx.y * 128, col0 = blockIdx.x * 128;
    const int car = tid >> 3, cg8 = tid & 7;

    GEMM_MAINLOOP(Ahi, Alo, Whib, Wlob, Mr)

    const int quad = lane >> 2, tq = lane & 3;
    #pragma unroll
    for (int mt = 0; mt < 2; mt++) {
        #pragma unroll
        for (int nt = 0; nt < 8; nt++) {
            int gr0 = row0 + wm * 32 + mt * 16 + quad;
            int gc  = col0 + wn * 64 + nt * 8 + tq * 2;
            float b0 = bias ? bias[gc]     : 0.f;
            float b1 = bias ? bias[gc + 1] : 0.f;
            #pragma unroll
            for (int half = 0; half < 2; half++) {
                int gr = gr0 + half * 8;
                if (gr < Mr) {
                    float2 v = {acc[mt][nt][half*2+0] + b0, acc[mt][nt][half*2+1] + b1};
                    *(float2*)&Cm[(size_t)gr * ldc + gc] = v;
                }
            }
        }
    }
}

// ---- fused Q+KV(+pos) GEMM ----
// by 0..69: q/kv projection (A rows 0..8951, cols 0..1535).
// by 70,71: pos projection (A rows 8960..9215, W_pos region, cols 0..511);
//           epilogue writes g_pos fp32 + g_poshi/lo bf16.
__global__ __launch_bounds__(256, 2) void gemm_qkv_kernel(
    const float* __restrict__ b_q, const float* __restrict__ b_kv,
    const float* __restrict__ pbu)
{
    const int row0 = blockIdx.y * 128, col0 = blockIdx.x * 128;
    const bool is_pos = (blockIdx.y >= 70);
    if (is_pos && col0 >= 512) return;

    extern __shared__ char gsm[];
    const uint32_t sb = smem_u32(gsm);
    const int tid = threadIdx.x;
    const int wid = tid >> 5, lane = tid & 31;
    const int wm = wid & 3, wn = wid >> 2;
    const int car = tid >> 3, cg8 = tid & 7;

    const __nv_bfloat16* WHIp = g_whi + (is_pos ? (size_t)2048 * 512 : 0);
    const __nv_bfloat16* WLOp = g_wlo + (is_pos ? (size_t)2048 * 512 : 0);

    GEMM_MAINLOOP(g_ahi, g_alo, WHIp, WLOp, 9216)

    const int quad = lane >> 2, tq = lane & 3;
    if (is_pos) {
        #pragma unroll
        for (int mt = 0; mt < 2; mt++) {
            #pragma unroll
            for (int nt = 0; nt < 8; nt++) {
                int gr0 = row0 + wm * 32 + mt * 16 + quad;
                int gc  = col0 + wn * 64 + nt * 8 + tq * 2;
                #pragma unroll
                for (int half = 0; half < 2; half++) {
                    int pl = gr0 + half * 8 - 8960;
                    float2 v = {acc[mt][nt][half*2+0], acc[mt][nt][half*2+1]};
                    *(float2*)&g_pos[(size_t)pl * 512 + gc] = v;
                    uint32_t hi, lo;
                    pack_hl(v.x, v.y, hi, lo);
                    *(uint32_t*)&g_poshi[(size_t)pl * 512 + gc] = hi;
                    *(uint32_t*)&g_poslo[(size_t)pl * 512 + gc] = lo;
                }
            }
        }
        return;
    }

    const bool is_q = (col0 < 512);
    #pragma unroll
    for (int mt = 0; mt < 2; mt++) {
        #pragma unroll
        for (int nt = 0; nt < 8; nt++) {
            int gr0 = row0 + wm * 32 + mt * 16 + quad;
            int gc  = col0 + wn * 64 + nt * 8 + tq * 2;
            #pragma unroll
            for (int half = 0; half < 2; half++) {
                int gr = gr0 + half * 8;
                if (gr >= 8952) continue;
                float2 v = {acc[mt][nt][half*2+0], acc[mt][nt][half*2+1]};
                if (is_q) {
                    int qr = gr - 120;
                    if (qr >= 0) {
                        v.x += b_q[gc] + pbu[gc];
                        v.y += b_q[gc + 1] + pbu[gc + 1];
                        uint32_t hi, lo;
                        pack_hl(v.x, v.y, hi, lo);
                        *(uint32_t*)&g_qhi[(size_t)qr * 512 + gc] = hi;
                        *(uint32_t*)&g_qlo[(size_t)qr * 512 + gc] = lo;
                    }
                } else {
                    int kc = gc - 512;
                    if (gr < 8824) {
                        v.x += b_kv[kc]; v.y += b_kv[kc + 1];
                        uint32_t hi, lo;
                        pack_hl(v.x, v.y, hi, lo);
                        *(uint32_t*)&g_kvhi[(size_t)gr * 1024 + kc] = hi;
                        *(uint32_t*)&g_kvlo[(size_t)gr * 1024 + kc] = lo;
                    }
                }
            }
        }
    }
}

// =====================================================================
// ps kernel: g_ps[bh][u][pl] = (q+pbu).pos^T + dvp[h][pl] via HMMA.
// grid (16 u-tiles of 64, 64 bh), 256 threads, 64KB smem -> 2 CTA/SM.
// =====================================================================
#define PS_TOTAL 65536

__global__ __launch_bounds__(256) void ps_kernel()
{
    extern __shared__ char psm[];
    const uint32_t sb = smem_u32(psm);
    const int ut = blockIdx.x, bh = blockIdx.y;
    const int b = bh >> 3, h = bh & 7;
    const int tid = threadIdx.x;
    const int wid = tid >> 5, lane = tid & 31;

    for (int idx = tid; idx < 192 * 8; idx += 256) {
        int r = idx >> 3, ch = idx & 7;
        size_t go = (size_t)r * 512 + h * 64 + ch * 8;
        uint32_t so = SWZ128((uint32_t)(r * 128 + ch * 16));
        cpa16(sb + 16384 + so, g_poshi + go);
        cpa16(sb + 40960 + so, g_poslo + go);
    }
    for (int idx = tid; idx < 64 * 8; idx += 256) {
        int r = idx >> 3, ch = idx & 7;
        int qrow = R_ + ut * 64 + r;
        size_t go = ((size_t)qrow * B_ + b) * 512 + h * 64 + ch * 8;
        uint32_t so = SWZ128((uint32_t)(r * 128 + ch * 16));
        cpa16(sb + so, g_qhi + go);
        cpa16(sb + 8192 + so, g_qlo + go);
    }
    CPA_COMMIT();
    CPA_WAIT0();
    __syncthreads();

    const int wm = wid >> 2, wn = wid & 3;
    const int l15 = lane & 15, lh = lane >> 4;
    const int l8 = lane & 7, lg = lane >> 3;
    const int quad = lane >> 2, tq = lane & 3;

    float acc[2][3][2][4] = {};
    #pragma unroll
    for (int pass = 0; pass < 3; pass++) {
        const uint32_t Ab = sb + ((pass == 1) ? 8192 : 0);
        const uint32_t Bb = sb + ((pass == 2) ? 40960 : 16384);
        #pragma unroll
        for (int s = 0; s < 4; s++) {
            uint32_t afr[2][4];
            #pragma unroll
            for (int mi = 0; mi < 2; mi++) {
                int r = (wm * 2 + mi) * 16 + l15;
                ldmx4(afr[mi], Ab + SWZ128((uint32_t)(r * 128 + s * 32 + lh * 16)));
            }
            #pragma unroll
            for (int nj = 0; nj < 3; nj++) {
                uint32_t bfr[4];
                int n = (wn + 4 * nj) * 16 + ((lg >> 1) ? 8 : 0) + l8;
                ldmx4(bfr, Bb + SWZ128((uint32_t)(n * 128 + s * 32 + (lg & 1) * 16)));
                #pragma unroll
                for (int mi = 0; mi < 2; mi++) {
                    mma16816(acc[mi][nj][0], afr[mi], bfr[0], bfr[1]);
                    mma16816(acc[mi][nj][1], afr[mi], bfr[2], bfr[3]);
                }
            }
        }
    }
    #pragma unroll
    for (int mi = 0; mi < 2; mi++) {
        #pragma unroll
        for (int nj = 0; nj < 3; nj++) {
            #pragma unroll
            for (int nh = 0; nh < 2; nh++) {
                int col = (wn + 4 * nj) * 16 + nh * 8 + tq * 2;
                float2 dv = *(const float2*)&g_dvp[h * 192 + col];
                #pragma unroll
                for (int hf = 0; hf < 2; hf++) {
                    int r = (wm * 2 + mi) * 16 + quad + hf * 8;
                    int u = ut * 64 + r;
                    *(float2*)&g_ps[((size_t)bh * 1024 + u) * 192 + col] =
                        make_float2(acc[mi][nj][nh][hf * 2 + 0] + dv.x,
                                    acc[mi][nj][nh][hf * 2 + 1] + dv.y);
                }
            }
        }
    }
}

// =====================================================================
// Fused attention v8: cp.async operands; summary rows clipped to d_out.
// 512 threads, 113280B smem -> 2 CTAs/SM.
// =====================================================================
#define FZ_QHI 0
#define FZ_QLO 10240
#define FZ_KHI 20480
#define FZ_KLO 40960
#define FZ_SS  61440
#define FZ_PHI 61440
#define FZ_PLO 84624
#define FZ_TOTAL 113280

__global__ __launch_bounds__(512, 2) void fused_attn_kernel(
    const int* __restrict__ lengths, float* __restrict__ outp)
{
    extern __shared__ char fsm[];
    const uint32_t sb = smem_u32(fsm);

    const int c = blockIdx.x, bh = blockIdx.y;
    const int b = bh >> 3, h = bh & 7;
    const int tid = threadIdx.x;
    const int wid = tid >> 5, lane = tid & 31;
    const int ustart = (c == 0) ? 0 : (c - 1) * CL_;
    const int ncols = c + 4 + ((c == 0) ? 64 : 128);
    const int len_b = lengths[b];
    const int pbase = (c == 0) ? 127 : 63;

    for (int idx = tid; idx < 69 * 8; idx += 512) {
        int r = idx >> 3, ch = idx & 7;
        int qrow = (r < 4) ? c * 4 + r
                 : (r < 68 ? R_ + c * 64 + (r - 4) : R_ + U_ + c);
        size_t go = ((size_t)qrow * B_ + b) * 512 + h * 64 + ch * 8;
        uint32_t so = SWZ128((uint32_t)(r * 128 + ch * 16));
        cpa16(sb + FZ_QHI + so, g_qhi + go);
        cpa16(sb + FZ_QLO + so, g_qlo + go);
    }
    for (int idx = tid; idx < ncols * 8; idx += 512) {
        int r = idx >> 3, ch = idx & 7;
        int kvrow = kv_row_of(r, c, ustart);
        size_t go = ((size_t)kvrow * B_ + b) * 1024 + h * 64 + ch * 8;
        uint32_t so = SWZ128((uint32_t)(r * 128 + ch * 16));
        cpa16(sb + FZ_KHI + so, g_kvhi + go);
        cpa16(sb + FZ_KLO + so, g_kvlo + go);
    }
    CPA_COMMIT();
    CPA_WAIT0();
    __syncthreads();

    const int l15 = lane & 15, lh = lane >> 4;
    const int l8 = lane & 7, lg = lane >> 3;
    const int quad = lane >> 2, tq = lane & 3;
    const int wmc = wid / 3, wnc = wid % 3;

    // ---- C1: scores = (Q+pbu).K^T (HMMA, 3 passes) ----
    if (wmc < 5) {
        float acc[4][2][4] = {};
        #pragma unroll
        for (int pass = 0; pass < 3; pass++) {
            const uint32_t Ab = sb + ((pass == 1) ? FZ_QLO : FZ_QHI);
            const uint32_t Bb = sb + ((pass == 2) ? FZ_KLO : FZ_KHI);
            #pragma unroll
            for (int s = 0; s < 4; s++) {
                uint32_t afr[4];
                ldmx4(afr, Ab + SWZ128((uint32_t)((wmc * 16 + l15) * 128 + s * 32 + lh * 16)));
                #pragma unroll
                for (int nj = 0; nj < 4; nj++) {
                    int nt = wnc + 3 * nj;
                    if (nt < 10) {
                        uint32_t bfr[4];
                        int n = nt * 16 + ((lg >> 1) ? 8 : 0) + l8;
                        ldmx4(bfr, Bb + SWZ128((uint32_t)(n * 128 + s * 32 + (lg & 1) * 16)));
                        mma16816(acc[nj][0], afr, bfr[0], bfr[1]);
                        mma16816(acc[nj][1], afr, bfr[2], bfr[3]);
                    }
                }
            }
        }
        #pragma unroll
        for (int nj = 0; nj < 4; nj++) {
            int nt = wnc + 3 * nj;
            if (nt < 10) {
                int r0 = wmc * 16 + quad;
                #pragma unroll
                for (int hf = 0; hf < 2; hf++) {
                    int col = nt * 16 + hf * 8 + tq * 2;
                    *(float2*)(fsm + FZ_SS + (size_t)r0 * 648 + col * 4) =
                        make_float2(acc[nj][hf][0], acc[nj][hf][1]);
                    *(float2*)(fsm + FZ_SS + (size_t)(r0 + 8) * 648 + col * 4) =
                        make_float2(acc[nj][hf][2], acc[nj][hf][3]);
                }
            }
        }
    }
    __syncthreads();

    // ---- V load via cp.async (overwrites K region) + zero pad rows ----
    {
        uint4 z = make_uint4(0, 0, 0, 0);
        for (int idx = tid; idx < (160 - ncols) * 8; idx += 512) {
            int r = ncols + (idx >> 3), ch = idx & 7;
            uint32_t so = SWZ128((uint32_t)(r * 128 + ch * 16));
            *(uint4*)(fsm + FZ_KHI + so) = z;
            *(uint4*)(fsm + FZ_KLO + so) = z;
        }
        for (int idx = tid; idx < ncols * 8; idx += 512) {
            int r = idx >> 3, ch = idx & 7;
            int kvrow = kv_row_of(r, c, ustart);
            size_t go = ((size_t)kvrow * B_ + b) * 1024 + 512 + h * 64 + ch * 8;
            uint32_t so = SWZ128((uint32_t)(r * 128 + ch * 16));
            cpa16(sb + FZ_KHI + so, g_kvhi + go);
            cpa16(sb + FZ_KLO + so, g_kvlo + go);
        }
        CPA_COMMIT();
    }

    // ---- softmax phase A (reads scores + g_ps band) ----
    float pvals[5][5];
    {
        const int limit_j = len_b - ustart;
        const int uc0 = c + 4;
        int slot = 0;
        for (int r = wid; r < 69; r += 16, slot++) {
            const bool is_utt = (r >= 4) && (r < 68);
            const int u_loc = r - 4;
            const float* psrow = g_ps + ((size_t)bh * 1024 + c * 64 + u_loc) * 192;
            const int plb = pbase - u_loc - uc0;
            float vals[5];
            float mx = -3.4e38f;
            #pragma unroll
            for (int g = 0; g < 5; g++) {
                int i = lane + 32 * g;
                float v = -3.4e38f;
                if (i < ncols) {
                    float s = *(const float*)(fsm + FZ_SS + (size_t)r * 648 + i * 4);
                    if (i >= uc0) {
                        int j = i - uc0;
                        if (is_utt) s += psrow[plb + i];
                        v = (j >= limit_j) ? NEG_INF_ : s * SCALING_;
                    } else {
                        v = s * SCALING_;
                    }
                }
                vals[g] = v;
                mx = fmaxf(mx, v);
            }
            #pragma unroll
            for (int o = 16; o > 0; o >>= 1) mx = fmaxf(mx, __shfl_xor_sync(~0u, mx, o));
            float sum = 0.f;
            #pragma unroll
            for (int g = 0; g < 5; g++) {
                float e = __expf(vals[g] - mx);
                vals[g] = e;
                sum += e;
            }
            #pragma unroll
            for (int o = 16; o > 0; o >>= 1) sum += __shfl_xor_sync(~0u, sum, o);
            float inv = 1.f / sum;
            #pragma unroll
            for (int g = 0; g < 5; g++) pvals[slot][g] = vals[g] * inv;
        }
    }
    __syncthreads();

    // ---- phase B: write P bf16 hi/lo over dead score region ----
    {
        int slot = 0;
        for (int r = wid; r < 69; r += 16, slot++) {
            #pragma unroll
            for (int g = 0; g < 5; g++) {
                int i = lane + 32 * g;
                float p = (i < ncols) ? pvals[slot][g] : 0.f;
                __nv_bfloat16 hp = __float2bfloat16(p);
                __nv_bfloat16 lp = __float2bfloat16(p - __bfloat162float(hp));
                *(ushort*)(fsm + FZ_PHI + r * 336 + i * 2) = __bfloat16_as_ushort(hp);
                *(ushort*)(fsm + FZ_PLO + r * 336 + i * 2) = __bfloat16_as_ushort(lp);
            }
        }
    }
    CPA_WAIT0();
    __syncthreads();

    // ---- PV: out = P.V (HMMA, 3 passes) ----
    {
        const int wmp = wid >> 2, wnp = wid & 3;
        float accp[2][2][4] = {};
        #pragma unroll
        for (int pass = 0; pass < 3; pass++) {
            const uint32_t Ab = sb + ((pass == 1) ? FZ_PLO : FZ_PHI);
            const uint32_t Bb = sb + ((pass == 2) ? FZ_KLO : FZ_KHI);
            #pragma unroll
            for (int kk = 0; kk < 10; kk++) {
                uint32_t bfr[4];
                ldmx4t(bfr, Bb + SWZ128((uint32_t)((kk * 16 + l15) * 128 + wnp * 32 + lh * 16)));
                #pragma unroll
                for (int mi = 0; mi < 2; mi++) {
                    int m = wmp + 4 * mi;
                    if (m < 5) {
                        uint32_t afr[4];
                        ldmx4(afr, Ab + (uint32_t)((m * 16 + l15) * 336 + kk * 32 + lh * 16));
                        mma16816(accp[mi][0], afr, bfr[0], bfr[1]);
                        mma16816(accp[mi][1], afr, bfr[2], bfr[3]);
                    }
                }
            }
        }
        #pragma unroll
        for (int mi = 0; mi < 2; mi++) {
            int m = wmp + 4 * mi;
            if (m >= 5) continue;
            int r0 = m * 16 + quad;
            #pragma unroll
            for (int hf = 0; hf < 2; hf++) {
                int r = r0 + hf * 8;
                if (r < 68) {
                    int qrow = (r < 4) ? c * 4 + r : R_ + c * 64 + (r - 4);
                    size_t base = ((size_t)qrow * B_ + b) * 512 + h * 64;
                    #pragma unroll
                    for (int n = 0; n < 2; n++) {
                        int d = wnp * 16 + n * 8 + tq * 2;
                        uint32_t vhi, vlo;
                        pack_hl(accp[mi][n][hf*2+0], accp[mi][n][hf*2+1], vhi, vlo);
                        *(uint32_t*)&g_ahi[base + d] = vhi;
                        *(uint32_t*)&g_alo[base + d] = vlo;
                    }
                } else if (r == 68) {
                    // summary row: clip and write directly to d_out
                    int qrow = R_ + U_ + c;
                    float* dst = outp + ((size_t)qrow * B_ + b) * 512 + h * 64;
                    #pragma unroll
                    for (int n = 0; n < 2; n++) {
                        int d = wnp * 16 + n * 8 + tq * 2;
                        float2 v = {accp[mi][n][hf*2+0], accp[mi][n][hf*2+1]};
                        v.x = fminf(10.f, fmaxf(-10.f, v.x));
                        v.y = fminf(10.f, fmaxf(-10.f, v.y));
                        *(float2*)(dst + d) = v;
                    }
                }
            }
        }
    }
}

// ---------------- launch ----------------
extern "C" void kernel_launch(void* const* d_in, const int* in_sizes, int n_in,
                              void* d_out, int out_size)
{
    const float* utt    = (const float*)d_in[0];
    const int*   lens   = (const int*)  d_in[1];
    const float* rc     = (const float*)d_in[2];
    const float* summ   = (const float*)d_in[3];
    const float* mem    = (const float*)d_in[4];
    const float* pos_e  = (const float*)d_in[6];
    const float* W_kv   = (const float*)d_in[7];
    const float* b_kv   = (const float*)d_in[8];
    const float* W_q    = (const float*)d_in[9];
    const float* b_q    = (const float*)d_in[10];
    const float* W_out  = (const float*)d_in[11];
    const float* b_out  = (const float*)d_in[12];
    const float* W_pos  = (const float*)d_in[13];
    const float* pbu    = (const float*)d_in[14];
    const float* pbv    = (const float*)d_in[15];
    float* out = (float*)d_out;

    __nv_bfloat16 *ahi, *alo, *whi, *wlo;
    cudaGetSymbolAddress((void**)&ahi, g_ahi);
    cudaGetSymbolAddress((void**)&alo, g_alo);
    cudaGetSymbolAddress((void**)&whi, g_whi);
    cudaGetSymbolAddress((void**)&wlo, g_wlo);

    cudaFuncSetAttribute(fused_attn_kernel,
                         cudaFuncAttributeMaxDynamicSharedMemorySize, FZ_TOTAL);
    cudaFuncSetAttribute(ps_kernel,
                         cudaFuncAttributeMaxDynamicSharedMemorySize, PS_TOTAL);
    cudaFuncSetAttribute(gemm_tc_kernel,
                         cudaFuncAttributeMaxDynamicSharedMemorySize, GSM_TOTAL);
    cudaFuncSetAttribute(gemm_qkv_kernel,
                         cudaFuncAttributeMaxDynamicSharedMemorySize, GSM_TOTAL);

    const dim3 blk(256);
    const float* pos_src = pos_e + (size_t)(U_ - 128) * D_;

    // ---- conversions ----
    conv_a_kernel<<<dim3((8952 * 128 + 255) / 256), blk>>>(
        mem, rc, utt, summ, 120, 632, 8824, 8952, 0);
    conv_a_kernel<<<dim3((191 * 128 + 255) / 256), blk>>>(
        pos_src, pos_src, pos_src, pos_src, 191, 191, 191, 191, 8960);
    conv_w_all<<<dim3(2560 * 512 / 256), blk>>>(W_q, W_kv, W_out, W_pos);

    // ---- fused Q+KV+pos projection (pos rides the tail wave) ----
    gemm_qkv_kernel<<<dim3(12, 72), blk, GSM_TOTAL>>>(b_q, b_kv, pbu);

    // ---- dvp correction, posS band, fused attention ----
    dvp_kernel<<<dim3(8), blk>>>(pbu, pbv);
    ps_kernel<<<dim3(16, 64), blk, PS_TOTAL>>>();
    fused_attn_kernel<<<dim3(C_, 64), dim3(512), FZ_TOTAL>>>(lens, out);

    // ---- output projection (rc+utt rows) ----
    gemm_tc_kernel<<<dim3(4, 68), blk, GSM_TOTAL>>>(
        ahi, alo, whi + (size_t)1536 * 512, wlo + (size_t)1536 * 512,
        out, (R_ + U_) * B_, D_, b_out);
}

// round 16
// speedup vs baseline: 1.2063x; 1.0031x over previous
#include <cuda_runtime.h>
#include <cuda_bf16.h>
#include <cstddef>
#include <cstdint>

// ---------------- problem constants ----------------
#define U_  1024
#define B_  8
#define D_  512
#define H_  8
#define HD_ 64
#define CL_ 64
#define RC_ 4
#define C_  16
#define R_  64
#define S_  16
#define M_  15
#define Q_  1104
#define KV_ 1103
#define NEG_INF_ (-100000000.0f)
#define SCALING_ 0.125f

typedef unsigned long long u64t;

// ---------------- mma / async helpers ----------------
__device__ __forceinline__ uint32_t smem_u32(const void* p) {
    uint32_t a;
    asm("{ .reg .u64 t; cvta.to.shared.u64 t, %1; cvt.u32.u64 %0, t; }" : "=r"(a) : "l"(p));
    return a;
}
#define SWZ128(o) ((o) ^ (((o) >> 3) & 0x70))

__device__ __forceinline__ void ldmx4(uint32_t* r, uint32_t addr) {
    asm volatile("ldmatrix.sync.aligned.m8n8.x4.shared.b16 {%0,%1,%2,%3}, [%4];"
                 : "=r"(r[0]), "=r"(r[1]), "=r"(r[2]), "=r"(r[3]) : "r"(addr));
}
__device__ __forceinline__ void ldmx4t(uint32_t* r, uint32_t addr) {
    asm volatile("ldmatrix.sync.aligned.m8n8.x4.trans.shared.b16 {%0,%1,%2,%3}, [%4];"
                 : "=r"(r[0]), "=r"(r[1]), "=r"(r[2]), "=r"(r[3]) : "r"(addr));
}
__device__ __forceinline__ void mma16816(float* d, const uint32_t* a,
                                         uint32_t b0, uint32_t b1) {
    asm volatile(
        "mma.sync.aligned.m16n8k16.row.col.f32.bf16.bf16.f32 "
        "{%0,%1,%2,%3}, {%4,%5,%6,%7}, {%8,%9}, {%0,%1,%2,%3};"
        : "+f"(d[0]), "+f"(d[1]), "+f"(d[2]), "+f"(d[3])
        : "r"(a[0]), "r"(a[1]), "r"(a[2]), "r"(a[3]), "r"(b0), "r"(b1));
}
__device__ __forceinline__ void cpa16(uint32_t dst, const void* src) {
    asm volatile("cp.async.cg.shared.global [%0], [%1], 16;" :: "r"(dst), "l"(src));
}
#define CPA_COMMIT() asm volatile("cp.async.commit_group;" ::: "memory")
#define CPA_WAIT1()  asm volatile("cp.async.wait_group 1;" ::: "memory")
#define CPA_WAIT0()  asm volatile("cp.async.wait_group 0;" ::: "memory")

// pack two floats into bf16x2 hi and lo words
__device__ __forceinline__ void pack_hl(float x, float y, uint32_t& hi, uint32_t& lo) {
    __nv_bfloat16 h0 = __float2bfloat16(x), h1 = __float2bfloat16(y);
    __nv_bfloat16 l0 = __float2bfloat16(x - __bfloat162float(h0));
    __nv_bfloat16 l1 = __float2bfloat16(y - __bfloat162float(h1));
    hi = (uint32_t)__bfloat16_as_ushort(h0) | ((uint32_t)__bfloat16_as_ushort(h1) << 16);
    lo = (uint32_t)__bfloat16_as_ushort(l0) | ((uint32_t)__bfloat16_as_ushort(l1) << 16);
}

// ---------------- scratch (device globals; no allocs) ----------------
__device__ float g_pos[(size_t)256 * D_];           // fp32 pos (rows >=191 zero)
__device__ float g_ps[(size_t)64 * 1024 * 192];     // (q+pbv).pos^T band (dvp folded)
// weights: W_q 0..511 | W_kv 512..1535 | W_out 1536..2047 | W_pos 2048..2559
__device__ __nv_bfloat16 g_whi[(size_t)2560 * 512];
__device__ __nv_bfloat16 g_wlo[(size_t)2560 * 512];
// A concat: [mem 0-119|rc 120-631|utt 632-8823|summ 8824-8951|(gap)|pos 8960-9150]
// rows 0..8703 overwritten by attention output for the out-proj
__device__ __nv_bfloat16 g_ahi[(size_t)9216 * 512];
__device__ __nv_bfloat16 g_alo[(size_t)9216 * 512];
__device__ __nv_bfloat16 g_poshi[(size_t)256 * 512];
__device__ __nv_bfloat16 g_poslo[(size_t)256 * 512];
// q (with pbu+bias folded) and kv as bf16 hi/lo (no fp32 copies)
__device__ __nv_bfloat16 g_qhi[(size_t)Q_ * B_ * 512];
__device__ __nv_bfloat16 g_qlo[(size_t)Q_ * B_ * 512];
__device__ __nv_bfloat16 g_kvhi[(size_t)KV_ * B_ * 1024];
__device__ __nv_bfloat16 g_kvlo[(size_t)KV_ * B_ * 1024];

__device__ __forceinline__ int kv_row_of(int i, int c, int ustart) {
    return (i < c) ? i
         : (i < c + 4 ? M_ + c * 4 + (i - c)
                      : M_ + R_ + ustart + (i - c - 4));
}

// =====================================================================
// Mega conversion kernel: A concat + pos rows + all weights, one launch.
// Region 0: A rows 0..8951 (4 floats/thread)      [0, 8952*128)
// Region 1: pos rows -> dst 8960..9150            [+191*128)
// Region 2: weights 2560x512 (1 float/thread)     [+2560*512)
// =====================================================================
#define CONV_NA (8952 * 128)
#define CONV_NP (191 * 128)
#define CONV_NW (2560 * 512)
#define CONV_TOT (CONV_NA + CONV_NP + CONV_NW)

__global__ void conv_all_kernel(
    const float* __restrict__ utt, const float* __restrict__ rc,
    const float* __restrict__ summ, const float* __restrict__ mem,
    const float* __restrict__ pos_src,
    const float* __restrict__ Wq, const float* __restrict__ Wkv,
    const float* __restrict__ Wout, const float* __restrict__ Wpos)
{
    int i = blockIdx.x * 256 + threadIdx.x;
    if (i < CONV_NA + CONV_NP) {
        const float* src; int lr, drow, c4;
        if (i < CONV_NA) {
            int row = i >> 7; c4 = (i & 127) * 4;
            if (row < 120)       { src = mem;  lr = row; }
            else if (row < 632)  { src = rc;   lr = row - 120; }
            else if (row < 8824) { src = utt;  lr = row - 632; }
            else                 { src = summ; lr = row - 8824; }
            drow = row;
        } else {
            int j = i - CONV_NA;
            int row = j >> 7; c4 = (j & 127) * 4;
            src = pos_src; lr = row; drow = 8960 + row;
        }
        float4 v = *(const float4*)(src + (size_t)lr * 512 + c4);
        uint32_t h0, l0, h1, l1;
        pack_hl(v.x, v.y, h0, l0);
        pack_hl(v.z, v.w, h1, l1);
        size_t o = (size_t)drow * 512 + c4;
        *(uint2*)&g_ahi[o] = make_uint2(h0, h1);
        *(uint2*)&g_alo[o] = make_uint2(l0, l1);
    } else if (i < CONV_TOT) {
        int j = i - CONV_NA - CONV_NP;
        int row = j >> 9, col = j & 511;
        const float* src; int lr;
        if (row < 512)       { src = Wq;   lr = row; }
        else if (row < 1536) { src = Wkv;  lr = row - 512; }
        else if (row < 2048) { src = Wout; lr = row - 1536; }
        else                 { src = Wpos; lr = row - 2048; }
        float a = src[(size_t)lr * 512 + col];
        __nv_bfloat16 h = __float2bfloat16(a);
        g_whi[j] = h;
        g_wlo[j] = __float2bfloat16(a - __bfloat162float(h));
    }
}

// =====================================================================
// GEMM mainloop: 128x128 tile, cp.async 3-stage, 24 chunks
// =====================================================================
#define GSM_TOTAL 98304

#define GEMM_MAINLOOP(AHI, ALO, WHI, WLO, MRTOT)                                    \
    float acc[2][8][4] = {};                                                        \
    {                                                                               \
        auto issue = [&](int cc) {                                                  \
            const int seg = cc >> 3;                                                \
            const int k0 = (cc & 7) * 64;                                           \
            const __nv_bfloat16* asrc = (seg == 1) ? (ALO) : (AHI);                 \
            const __nv_bfloat16* wsrc = (seg == 2) ? (WLO) : (WHI);                 \
            char* abuf = gsm + (cc % 3) * 16384;                                    \
            char* bbuf = gsm + 49152 + (cc % 3) * 16384;                            \
            _Pragma("unroll")                                                       \
            for (int t = 0; t < 4; t++) {                                           \
                int ar = car + t * 32;                                              \
                int gr = row0 + ar; if (gr >= (MRTOT)) gr = (MRTOT) - 1;            \
                cpa16(smem_u32(abuf) + SWZ128((uint32_t)(ar * 128 + cg8 * 16)),     \
                      asrc + (size_t)gr * 512 + k0 + cg8 * 8);                      \
            }                                                                       \
            _Pragma("unroll")                                                       \
            for (int t = 0; t < 4; t++) {                                           \
                int br = car + t * 32;                                              \
                cpa16(smem_u32(bbuf) + SWZ128((uint32_t)(br * 128 + cg8 * 16)),     \
                      wsrc + (size_t)(col0 + br) * 512 + k0 + cg8 * 8);             \
            }                                                                       \
            CPA_COMMIT();                                                           \
        };                                                                          \
        issue(0);                                                                   \
        issue(1);                                                                   \
        const int l15 = lane & 15, lh = lane >> 4;                                  \
        const int l8 = lane & 7, lg = lane >> 3;                                    \
        for (int cc = 0; cc < 24; cc++) {                                           \
            if (cc < 23) CPA_WAIT1(); else CPA_WAIT0();                             \
            __syncthreads();                                                        \
            const uint32_t Ab = sb + (cc % 3) * 16384;                              \
            const uint32_t Bb = sb + 49152 + (cc % 3) * 16384;                      \
            _Pragma("unroll")                                                       \
            for (int s = 0; s < 4; s++) {                                           \
                uint32_t afr[2][4];                                                 \
                _Pragma("unroll")                                                   \
                for (int mt = 0; mt < 2; mt++) {                                    \
                    int r = wm * 32 + mt * 16 + l15;                                \
                    ldmx4(afr[mt], Ab + SWZ128((uint32_t)(r * 128 + s * 32 + lh * 16))); \
                }                                                                   \
                uint32_t bfr[4][4];                                                 \
                _Pragma("unroll")                                                   \
                for (int bt = 0; bt < 4; bt++) {                                    \
                    int n = wn * 64 + bt * 16 + ((lg >> 1) ? 8 : 0) + l8;           \
                    ldmx4(bfr[bt], Bb + SWZ128((uint32_t)(n * 128 + s * 32 + (lg & 1) * 16))); \
                }                                                                   \
                _Pragma("unroll")                                                   \
                for (int mt = 0; mt < 2; mt++)                                      \
                    _Pragma("unroll")                                               \
                    for (int nt = 0; nt < 8; nt++) {                                \
                        int bt = nt >> 1, sub = nt & 1;                             \
                        mma16816(acc[mt][nt], afr[mt], bfr[bt][2*sub], bfr[bt][2*sub+1]); \
                    }                                                               \
            }                                                                       \
            if (cc + 2 < 24) issue(cc + 2);                                         \
        }                                                                           \
    }

// ---- generic GEMM (out projection), fp32 out ----
__global__ __launch_bounds__(256, 2) void gemm_tc_kernel(
    const __nv_bfloat16* __restrict__ Ahi, const __nv_bfloat16* __restrict__ Alo,
    const __nv_bfloat16* __restrict__ Whib, const __nv_bfloat16* __restrict__ Wlob,
    float* __restrict__ Cm, int Mr, int ldc, const float* __restrict__ bias)
{
    extern __shared__ char gsm[];
    const uint32_t sb = smem_u32(gsm);
    const int tid = threadIdx.x;
    const int wid = tid >> 5, lane = tid & 31;
    const int wm = wid & 3, wn = wid >> 2;
    const int row0 = blockIdx.y * 128, col0 = blockIdx.x * 128;
    const int car = tid >> 3, cg8 = tid & 7;

    GEMM_MAINLOOP(Ahi, Alo, Whib, Wlob, Mr)

    const int quad = lane >> 2, tq = lane & 3;
    #pragma unroll
    for (int mt = 0; mt < 2; mt++) {
        #pragma unroll
        for (int nt = 0; nt < 8; nt++) {
            int gr0 = row0 + wm * 32 + mt * 16 + quad;
            int gc  = col0 + wn * 64 + nt * 8 + tq * 2;
            float b0 = bias ? bias[gc]     : 0.f;
            float b1 = bias ? bias[gc + 1] : 0.f;
            #pragma unroll
            for (int half = 0; half < 2; half++) {
                int gr = gr0 + half * 8;
                if (gr < Mr) {
                    float2 v = {acc[mt][nt][half*2+0] + b0, acc[mt][nt][half*2+1] + b1};
                    *(float2*)&Cm[(size_t)gr * ldc + gc] = v;
                }
            }
        }
    }
}

// ---- fused Q+KV(+pos) GEMM ----
__global__ __launch_bounds__(256, 2) void gemm_qkv_kernel(
    const float* __restrict__ b_q, const float* __restrict__ b_kv,
    const float* __restrict__ pbu)
{
    const int row0 = blockIdx.y * 128, col0 = blockIdx.x * 128;
    const bool is_pos = (blockIdx.y >= 70);
    if (is_pos && col0 >= 512) return;

    extern __shared__ char gsm[];
    const uint32_t sb = smem_u32(gsm);
    const int tid = threadIdx.x;
    const int wid = tid >> 5, lane = tid & 31;
    const int wm = wid & 3, wn = wid >> 2;
    const int car = tid >> 3, cg8 = tid & 7;

    const __nv_bfloat16* WHIp = g_whi + (is_pos ? (size_t)2048 * 512 : 0);
    const __nv_bfloat16* WLOp = g_wlo + (is_pos ? (size_t)2048 * 512 : 0);

    GEMM_MAINLOOP(g_ahi, g_alo, WHIp, WLOp, 9216)

    const int quad = lane >> 2, tq = lane & 3;
    if (is_pos) {
        #pragma unroll
        for (int mt = 0; mt < 2; mt++) {
            #pragma unroll
            for (int nt = 0; nt < 8; nt++) {
                int gr0 = row0 + wm * 32 + mt * 16 + quad;
                int gc  = col0 + wn * 64 + nt * 8 + tq * 2;
                #pragma unroll
                for (int half = 0; half < 2; half++) {
                    int pl = gr0 + half * 8 - 8960;
                    float2 v = {acc[mt][nt][half*2+0], acc[mt][nt][half*2+1]};
                    *(float2*)&g_pos[(size_t)pl * 512 + gc] = v;
                    uint32_t hi, lo;
                    pack_hl(v.x, v.y, hi, lo);
                    *(uint32_t*)&g_poshi[(size_t)pl * 512 + gc] = hi;
                    *(uint32_t*)&g_poslo[(size_t)pl * 512 + gc] = lo;
                }
            }
        }
        return;
    }

    const bool is_q = (col0 < 512);
    #pragma unroll
    for (int mt = 0; mt < 2; mt++) {
        #pragma unroll
        for (int nt = 0; nt < 8; nt++) {
            int gr0 = row0 + wm * 32 + mt * 16 + quad;
            int gc  = col0 + wn * 64 + nt * 8 + tq * 2;
            #pragma unroll
            for (int half = 0; half < 2; half++) {
                int gr = gr0 + half * 8;
                if (gr >= 8952) continue;
                float2 v = {acc[mt][nt][half*2+0], acc[mt][nt][half*2+1]};
                if (is_q) {
                    int qr = gr - 120;
                    if (qr >= 0) {
                        v.x += b_q[gc] + pbu[gc];
                        v.y += b_q[gc + 1] + pbu[gc + 1];
                        uint32_t hi, lo;
                        pack_hl(v.x, v.y, hi, lo);
                        *(uint32_t*)&g_qhi[(size_t)qr * 512 + gc] = hi;
                        *(uint32_t*)&g_qlo[(size_t)qr * 512 + gc] = lo;
                    }
                } else {
                    int kc = gc - 512;
                    if (gr < 8824) {
                        v.x += b_kv[kc]; v.y += b_kv[kc + 1];
                        uint32_t hi, lo;
                        pack_hl(v.x, v.y, hi, lo);
                        *(uint32_t*)&g_kvhi[(size_t)gr * 1024 + kc] = hi;
                        *(uint32_t*)&g_kvlo[(size_t)gr * 1024 + kc] = lo;
                    }
                }
            }
        }
    }
}

// =====================================================================
// ps kernel: g_ps[bh][u][pl] = (q+pbu).pos^T + (pbv-pbu).pos[pl].
// dvp computed in-kernel (smem) while cp.asyncs are in flight.
// grid (16 u-tiles of 64, 64 bh), 256 threads, ~65KB smem -> 2 CTA/SM.
// =====================================================================
#define PS_DVP 65536
#define PS_TOTAL (65536 + 768)

__global__ __launch_bounds__(256) void ps_kernel(
    const float* __restrict__ pbu, const float* __restrict__ pbv)
{
    extern __shared__ char psm[];
    const uint32_t sb = smem_u32(psm);
    float* dvp_s = (float*)(psm + PS_DVP);
    const int ut = blockIdx.x, bh = blockIdx.y;
    const int b = bh >> 3, h = bh & 7;
    const int tid = threadIdx.x;
    const int wid = tid >> 5, lane = tid & 31;

    for (int idx = tid; idx < 192 * 8; idx += 256) {
        int r = idx >> 3, ch = idx & 7;
        size_t go = (size_t)r * 512 + h * 64 + ch * 8;
        uint32_t so = SWZ128((uint32_t)(r * 128 + ch * 16));
        cpa16(sb + 16384 + so, g_poshi + go);
        cpa16(sb + 40960 + so, g_poslo + go);
    }
    for (int idx = tid; idx < 64 * 8; idx += 256) {
        int r = idx >> 3, ch = idx & 7;
        int qrow = R_ + ut * 64 + r;
        size_t go = ((size_t)qrow * B_ + b) * 512 + h * 64 + ch * 8;
        uint32_t so = SWZ128((uint32_t)(r * 128 + ch * 16));
        cpa16(sb + so, g_qhi + go);
        cpa16(sb + 8192 + so, g_qlo + go);
    }
    CPA_COMMIT();

    // dvp[pl] = (pbv-pbu)[h] . pos[pl] (fp32 exact; rows >=191 are zero)
    if (tid < 192) {
        int pl = tid;
        float s = 0.f;
        const float4* pp = (const float4*)(g_pos + (size_t)pl * 512 + h * 64);
        const float4* up = (const float4*)(pbu + h * 64);
        const float4* vp = (const float4*)(pbv + h * 64);
        #pragma unroll 4
        for (int k4 = 0; k4 < 16; k4++) {
            float4 a = pp[k4], uu = up[k4], vv = vp[k4];
            s += a.x * (vv.x - uu.x) + a.y * (vv.y - uu.y)
               + a.z * (vv.z - uu.z) + a.w * (vv.w - uu.w);
        }
        dvp_s[pl] = s;
    }
    CPA_WAIT0();
    __syncthreads();

    const int wm = wid >> 2, wn = wid & 3;
    const int l15 = lane & 15, lh = lane >> 4;
    const int l8 = lane & 7, lg = lane >> 3;
    const int quad = lane >> 2, tq = lane & 3;

    float acc[2][3][2][4] = {};
    #pragma unroll
    for (int pass = 0; pass < 3; pass++) {
        const uint32_t Ab = sb + ((pass == 1) ? 8192 : 0);
        const uint32_t Bb = sb + ((pass == 2) ? 40960 : 16384);
        #pragma unroll
        for (int s = 0; s < 4; s++) {
            uint32_t afr[2][4];
            #pragma unroll
            for (int mi = 0; mi < 2; mi++) {
                int r = (wm * 2 + mi) * 16 + l15;
                ldmx4(afr[mi], Ab + SWZ128((uint32_t)(r * 128 + s * 32 + lh * 16)));
            }
            #pragma unroll
            for (int nj = 0; nj < 3; nj++) {
                uint32_t bfr[4];
                int n = (wn + 4 * nj) * 16 + ((lg >> 1) ? 8 : 0) + l8;
                ldmx4(bfr, Bb + SWZ128((uint32_t)(n * 128 + s * 32 + (lg & 1) * 16)));
                #pragma unroll
                for (int mi = 0; mi < 2; mi++) {
                    mma16816(acc[mi][nj][0], afr[mi], bfr[0], bfr[1]);
                    mma16816(acc[mi][nj][1], afr[mi], bfr[2], bfr[3]);
                }
            }
        }
    }
    #pragma unroll
    for (int mi = 0; mi < 2; mi++) {
        #pragma unroll
        for (int nj = 0; nj < 3; nj++) {
            #pragma unroll
            for (int nh = 0; nh < 2; nh++) {
                int col = (wn + 4 * nj) * 16 + nh * 8 + tq * 2;
                float2 dv = *(const float2*)&dvp_s[col];
                #pragma unroll
                for (int hf = 0; hf < 2; hf++) {
                    int r = (wm * 2 + mi) * 16 + quad + hf * 8;
                    int u = ut * 64 + r;
                    *(float2*)&g_ps[((size_t)bh * 1024 + u) * 192 + col] =
                        make_float2(acc[mi][nj][nh][hf * 2 + 0] + dv.x,
                                    acc[mi][nj][nh][hf * 2 + 1] + dv.y);
                }
            }
        }
    }
}

// =====================================================================
// Fused attention v9: runtime-trimmed tiles; cp.async operands.
// 512 threads, 113280B smem -> 2 CTAs/SM.
// =====================================================================
#define FZ_QHI 0
#define FZ_QLO 10240
#define FZ_KHI 20480
#define FZ_KLO 40960
#define FZ_SS  61440
#define FZ_PHI 61440
#define FZ_PLO 84624
#define FZ_TOTAL 113280

__global__ __launch_bounds__(512, 2) void fused_attn_kernel(
    const int* __restrict__ lengths, float* __restrict__ outp)
{
    extern __shared__ char fsm[];
    const uint32_t sb = smem_u32(fsm);

    const int c = blockIdx.x, bh = blockIdx.y;
    const int b = bh >> 3, h = bh & 7;
    const int tid = threadIdx.x;
    const int wid = tid >> 5, lane = tid & 31;
    const int ustart = (c == 0) ? 0 : (c - 1) * CL_;
    const int ncols = c + 4 + ((c == 0) ? 64 : 128);
    const int ntiles = (ncols + 15) >> 4;       // live 16-col tiles
    const int len_b = lengths[b];
    const int pbase = (c == 0) ? 127 : 63;

    for (int idx = tid; idx < 69 * 8; idx += 512) {
        int r = idx >> 3, ch = idx & 7;
        int qrow = (r < 4) ? c * 4 + r
                 : (r < 68 ? R_ + c * 64 + (r - 4) : R_ + U_ + c);
        size_t go = ((size_t)qrow * B_ + b) * 512 + h * 64 + ch * 8;
        uint32_t so = SWZ128((uint32_t)(r * 128 + ch * 16));
        cpa16(sb + FZ_QHI + so, g_qhi + go);
        cpa16(sb + FZ_QLO + so, g_qlo + go);
    }
    for (int idx = tid; idx < ncols * 8; idx += 512) {
        int r = idx >> 3, ch = idx & 7;
        int kvrow = kv_row_of(r, c, ustart);
        size_t go = ((size_t)kvrow * B_ + b) * 1024 + h * 64 + ch * 8;
        uint32_t so = SWZ128((uint32_t)(r * 128 + ch * 16));
        cpa16(sb + FZ_KHI + so, g_kvhi + go);
        cpa16(sb + FZ_KLO + so, g_kvlo + go);
    }
    // zero K partial-tile pad rows (ncols .. ntiles*16-1)
    {
        uint4 z = make_uint4(0, 0, 0, 0);
        int npad = ntiles * 16 - ncols;
        for (int idx = tid; idx < npad * 8; idx += 512) {
            int r = ncols + (idx >> 3), ch = idx & 7;
            uint32_t so = SWZ128((uint32_t)(r * 128 + ch * 16));
            *(uint4*)(fsm + FZ_KHI + so) = z;
            *(uint4*)(fsm + FZ_KLO + so) = z;
        }
    }
    CPA_COMMIT();
    CPA_WAIT0();
    __syncthreads();

    const int l15 = lane & 15, lh = lane >> 4;
    const int l8 = lane & 7, lg = lane >> 3;
    const int quad = lane >> 2, tq = lane & 3;
    const int wmc = wid / 3, wnc = wid % 3;

    // ---- C1: scores = (Q+pbu).K^T (HMMA, 3 passes, live n-tiles only) ----
    if (wmc < 5) {
        float acc[4][2][4] = {};
        #pragma unroll
        for (int pass = 0; pass < 3; pass++) {
            const uint32_t Ab = sb + ((pass == 1) ? FZ_QLO : FZ_QHI);
            const uint32_t Bb = sb + ((pass == 2) ? FZ_KLO : FZ_KHI);
            #pragma unroll
            for (int s = 0; s < 4; s++) {
                uint32_t afr[4];
                ldmx4(afr, Ab + SWZ128((uint32_t)((wmc * 16 + l15) * 128 + s * 32 + lh * 16)));
                #pragma unroll
                for (int nj = 0; nj < 4; nj++) {
                    int nt = wnc + 3 * nj;
                    if (nt < ntiles) {
                        uint32_t bfr[4];
                        int n = nt * 16 + ((lg >> 1) ? 8 : 0) + l8;
                        ldmx4(bfr, Bb + SWZ128((uint32_t)(n * 128 + s * 32 + (lg & 1) * 16)));
                        mma16816(acc[nj][0], afr, bfr[0], bfr[1]);
                        mma16816(acc[nj][1], afr, bfr[2], bfr[3]);
                    }
                }
            }
        }
        #pragma unroll
        for (int nj = 0; nj < 4; nj++) {
            int nt = wnc + 3 * nj;
            if (nt < ntiles) {
                int r0 = wmc * 16 + quad;
                #pragma unroll
                for (int hf = 0; hf < 2; hf++) {
                    int col = nt * 16 + hf * 8 + tq * 2;
                    *(float2*)(fsm + FZ_SS + (size_t)r0 * 648 + col * 4) =
                        make_float2(acc[nj][hf][0], acc[nj][hf][1]);
                    *(float2*)(fsm + FZ_SS + (size_t)(r0 + 8) * 648 + col * 4) =
                        make_float2(acc[nj][hf][2], acc[nj][hf][3]);
                }
            }
        }
    }
    __syncthreads();

    // ---- V load via cp.async (overwrites K region) + zero partial pad ----
    {
        uint4 z = make_uint4(0, 0, 0, 0);
        int npad = ntiles * 16 - ncols;
        for (int idx = tid; idx < npad * 8; idx += 512) {
            int r = ncols + (idx >> 3), ch = idx & 7;
            uint32_t so = SWZ128((uint32_t)(r * 128 + ch * 16));
            *(uint4*)(fsm + FZ_KHI + so) = z;
            *(uint4*)(fsm + FZ_KLO + so) = z;
        }
        for (int idx = tid; idx < ncols * 8; idx += 512) {
            int r = idx >> 3, ch = idx & 7;
            int kvrow = kv_row_of(r, c, ustart);
            size_t go = ((size_t)kvrow * B_ + b) * 1024 + 512 + h * 64 + ch * 8;
            uint32_t so = SWZ128((uint32_t)(r * 128 + ch * 16));
            cpa16(sb + FZ_KHI + so, g_kvhi + go);
            cpa16(sb + FZ_KLO + so, g_kvlo + go);
        }
        CPA_COMMIT();
    }

    // ---- softmax phase A (reads scores + g_ps band) ----
    float pvals[5][5];
    {
        const int limit_j = len_b - ustart;
        const int uc0 = c + 4;
        int slot = 0;
        for (int r = wid; r < 69; r += 16, slot++) {
            const bool is_utt = (r >= 4) && (r < 68);
            const int u_loc = r - 4;
            const float* psrow = g_ps + ((size_t)bh * 1024 + c * 64 + u_loc) * 192;
            const int plb = pbase - u_loc - uc0;
            float vals[5];
            float mx = -3.4e38f;
            #pragma unroll
            for (int g = 0; g < 5; g++) {
                int i = lane + 32 * g;
                float v = -3.4e38f;
                if (i < ncols) {
                    float s = *(const float*)(fsm + FZ_SS + (size_t)r * 648 + i * 4);
                    if (i >= uc0) {
                        int j = i - uc0;
                        if (is_utt) s += psrow[plb + i];
                        v = (j >= limit_j) ? NEG_INF_ : s * SCALING_;
                    } else {
                        v = s * SCALING_;
                    }
                }
                vals[g] = v;
                mx = fmaxf(mx, v);
            }
            #pragma unroll
            for (int o = 16; o > 0; o >>= 1) mx = fmaxf(mx, __shfl_xor_sync(~0u, mx, o));
            float sum = 0.f;
            #pragma unroll
            for (int g = 0; g < 5; g++) {
                float e = __expf(vals[g] - mx);
                vals[g] = e;
                sum += e;
            }
            #pragma unroll
            for (int o = 16; o > 0; o >>= 1) sum += __shfl_xor_sync(~0u, sum, o);
            float inv = 1.f / sum;
            #pragma unroll
            for (int g = 0; g < 5; g++) pvals[slot][g] = vals[g] * inv;
        }
    }
    __syncthreads();

    // ---- phase B: write P bf16 hi/lo over dead score region ----
    {
        int slot = 0;
        for (int r = wid; r < 69; r += 16, slot++) {
            #pragma unroll
            for (int g = 0; g < 5; g++) {
                int i = lane + 32 * g;
                float p = (i < ncols) ? pvals[slot][g] : 0.f;
                __nv_bfloat16 hp = __float2bfloat16(p);
                __nv_bfloat16 lp = __float2bfloat16(p - __bfloat162float(hp));
                *(ushort*)(fsm + FZ_PHI + r * 336 + i * 2) = __bfloat16_as_ushort(hp);
                *(ushort*)(fsm + FZ_PLO + r * 336 + i * 2) = __bfloat16_as_ushort(lp);
            }
        }
    }
    CPA_WAIT0();
    __syncthreads();

    // ---- PV: out = P.V (HMMA, 3 passes, live k-tiles only) ----
    {
        const int wmp = wid >> 2, wnp = wid & 3;
        float accp[2][2][4] = {};
        #pragma unroll
        for (int pass = 0; pass < 3; pass++) {
            const uint32_t Ab = sb + ((pass == 1) ? FZ_PLO : FZ_PHI);
            const uint32_t Bb = sb + ((pass == 2) ? FZ_KLO : FZ_KHI);
            for (int kk = 0; kk < ntiles; kk++) {
                uint32_t bfr[4];
                ldmx4t(bfr, Bb + SWZ128((uint32_t)((kk * 16 + l15) * 128 + wnp * 32 + lh * 16)));
                #pragma unroll
                for (int mi = 0; mi < 2; mi++) {
                    int m = wmp + 4 * mi;
                    if (m < 5) {
                        uint32_t afr[4];
                        ldmx4(afr, Ab + (uint32_t)((m * 16 + l15) * 336 + kk * 32 + lh * 16));
                        mma16816(accp[mi][0], afr, bfr[0], bfr[1]);
                        mma16816(accp[mi][1], afr, bfr[2], bfr[3]);
                    }
                }
            }
        }
        #pragma unroll
        for (int mi = 0; mi < 2; mi++) {
            int m = wmp + 4 * mi;
            if (m >= 5) continue;
            int r0 = m * 16 + quad;
            #pragma unroll
            for (int hf = 0; hf < 2; hf++) {
                int r = r0 + hf * 8;
                if (r < 68) {
                    int qrow = (r < 4) ? c * 4 + r : R_ + c * 64 + (r - 4);
                    size_t base = ((size_t)qrow * B_ + b) * 512 + h * 64;
                    #pragma unroll
                    for (int n = 0; n < 2; n++) {
                        int d = wnp * 16 + n * 8 + tq * 2;
                        uint32_t vhi, vlo;
                        pack_hl(accp[mi][n][hf*2+0], accp[mi][n][hf*2+1], vhi, vlo);
                        *(uint32_t*)&g_ahi[base + d] = vhi;
                        *(uint32_t*)&g_alo[base + d] = vlo;
                    }
                } else if (r == 68) {
                    int qrow = R_ + U_ + c;
                    float* dst = outp + ((size_t)qrow * B_ + b) * 512 + h * 64;
                    #pragma unroll
                    for (int n = 0; n < 2; n++) {
                        int d = wnp * 16 + n * 8 + tq * 2;
                        float2 v = {accp[mi][n][hf*2+0], accp[mi][n][hf*2+1]};
                        v.x = fminf(10.f, fmaxf(-10.f, v.x));
                        v.y = fminf(10.f, fmaxf(-10.f, v.y));
                        *(float2*)(dst + d) = v;
                    }
                }
            }
        }
    }
}

// ---------------- launch ----------------
extern "C" void kernel_launch(void* const* d_in, const int* in_sizes, int n_in,
                              void* d_out, int out_size)
{
    const float* utt    = (const float*)d_in[0];
    const int*   lens   = (const int*)  d_in[1];
    const float* rc     = (const float*)d_in[2];
    const float* summ   = (const float*)d_in[3];
    const float* mem    = (const float*)d_in[4];
    const float* pos_e  = (const float*)d_in[6];
    const float* W_kv   = (const float*)d_in[7];
    const float* b_kv   = (const float*)d_in[8];
    const float* W_q    = (const float*)d_in[9];
    const float* b_q    = (const float*)d_in[10];
    const float* W_out  = (const float*)d_in[11];
    const float* b_out  = (const float*)d_in[12];
    const float* W_pos  = (const float*)d_in[13];
    const float* pbu    = (const float*)d_in[14];
    const float* pbv    = (const float*)d_in[15];
    float* out = (float*)d_out;

    __nv_bfloat16 *ahi, *alo, *whi, *wlo;
    cudaGetSymbolAddress((void**)&ahi, g_ahi);
    cudaGetSymbolAddress((void**)&alo, g_alo);
    cudaGetSymbolAddress((void**)&whi, g_whi);
    cudaGetSymbolAddress((void**)&wlo, g_wlo);

    cudaFuncSetAttribute(fused_attn_kernel,
                         cudaFuncAttributeMaxDynamicSharedMemorySize, FZ_TOTAL);
    cudaFuncSetAttribute(ps_kernel,
                         cudaFuncAttributeMaxDynamicSharedMemorySize, PS_TOTAL);
    cudaFuncSetAttribute(gemm_tc_kernel,
                         cudaFuncAttributeMaxDynamicSharedMemorySize, GSM_TOTAL);
    cudaFuncSetAttribute(gemm_qkv_kernel,
                         cudaFuncAttributeMaxDynamicSharedMemorySize, GSM_TOTAL);

    const dim3 blk(256);
    const float* pos_src = pos_e + (size_t)(U_ - 128) * D_;

    // ---- all conversions in one launch ----
    conv_all_kernel<<<dim3((CONV_TOT + 255) / 256), blk>>>(
        utt, rc, summ, mem, pos_src, W_q, W_kv, W_out, W_pos);

    // ---- fused Q+KV+pos projection (pos rides the tail wave) ----
    gemm_qkv_kernel<<<dim3(12, 72), blk, GSM_TOTAL>>>(b_q, b_kv, pbu);

    // ---- posS band (dvp folded), fused attention ----
    ps_kernel<<<dim3(16, 64), blk, PS_TOTAL>>>(pbu, pbv);
    fused_attn_kernel<<<dim3(C_, 64), dim3(512), FZ_TOTAL>>>(lens, out);

    // ---- output projection (rc+utt rows) ----
    gemm_tc_kernel<<<dim3(4, 68), blk, GSM_TOTAL>>>(
        ahi, alo, whi + (size_t)1536 * 512, wlo + (size_t)1536 * 512,
        out, (R_ + U_) * B_, D_, b_out);
}

// round 17
// speedup vs baseline: 1.2713x; 1.0539x over previous
#include <cuda_runtime.h>
#include <cuda_bf16.h>
#include <cstddef>
#include <cstdint>

// ---------------- problem constants ----------------
#define U_  1024
#define B_  8
#define D_  512
#define H_  8
#define HD_ 64
#define CL_ 64
#define RC_ 4
#define C_  16
#define R_  64
#define S_  16
#define M_  15
#define Q_  1104
#define KV_ 1103
#define NEG_INF_ (-100000000.0f)
#define SCALING_ 0.125f

typedef unsigned long long u64t;

// ---------------- mma / async helpers ----------------
__device__ __forceinline__ uint32_t smem_u32(const void* p) {
    uint32_t a;
    asm("{ .reg .u64 t; cvta.to.shared.u64 t, %1; cvt.u32.u64 %0, t; }" : "=r"(a) : "l"(p));
    return a;
}
#define SWZ128(o) ((o) ^ (((o) >> 3) & 0x70))

__device__ __forceinline__ void ldmx4(uint32_t* r, uint32_t addr) {
    asm volatile("ldmatrix.sync.aligned.m8n8.x4.shared.b16 {%0,%1,%2,%3}, [%4];"
                 : "=r"(r[0]), "=r"(r[1]), "=r"(r[2]), "=r"(r[3]) : "r"(addr));
}
__device__ __forceinline__ void ldmx4t(uint32_t* r, uint32_t addr) {
    asm volatile("ldmatrix.sync.aligned.m8n8.x4.trans.shared.b16 {%0,%1,%2,%3}, [%4];"
                 : "=r"(r[0]), "=r"(r[1]), "=r"(r[2]), "=r"(r[3]) : "r"(addr));
}
__device__ __forceinline__ void mma16816(float* d, const uint32_t* a,
                                         uint32_t b0, uint32_t b1) {
    asm volatile(
        "mma.sync.aligned.m16n8k16.row.col.f32.bf16.bf16.f32 "
        "{%0,%1,%2,%3}, {%4,%5,%6,%7}, {%8,%9}, {%0,%1,%2,%3};"
        : "+f"(d[0]), "+f"(d[1]), "+f"(d[2]), "+f"(d[3])
        : "r"(a[0]), "r"(a[1]), "r"(a[2]), "r"(a[3]), "r"(b0), "r"(b1));
}
__device__ __forceinline__ void cpa16(uint32_t dst, const void* src) {
    asm volatile("cp.async.cg.shared.global [%0], [%1], 16;" :: "r"(dst), "l"(src));
}
#define CPA_COMMIT() asm volatile("cp.async.commit_group;" ::: "memory")
#define CPA_WAIT1()  asm volatile("cp.async.wait_group 1;" ::: "memory")
#define CPA_WAIT0()  asm volatile("cp.async.wait_group 0;" ::: "memory")

// pack two floats into bf16x2 hi and lo words
__device__ __forceinline__ void pack_hl(float x, float y, uint32_t& hi, uint32_t& lo) {
    __nv_bfloat16 h0 = __float2bfloat16(x), h1 = __float2bfloat16(y);
    __nv_bfloat16 l0 = __float2bfloat16(x - __bfloat162float(h0));
    __nv_bfloat16 l1 = __float2bfloat16(y - __bfloat162float(h1));
    hi = (uint32_t)__bfloat16_as_ushort(h0) | ((uint32_t)__bfloat16_as_ushort(h1) << 16);
    lo = (uint32_t)__bfloat16_as_ushort(l0) | ((uint32_t)__bfloat16_as_ushort(l1) << 16);
}

// ---------------- scratch (device globals; no allocs) ----------------
__device__ float g_pos[(size_t)256 * D_];           // fp32 pos (rows >=191 zero)
__device__ float g_psc[(size_t)64 * 1024 * 128];    // compact band: [bh][u][j], j = i-uc0
// weights: W_q 0..511 | W_kv 512..1535 | W_out 1536..2047 | W_pos 2048..2559
__device__ __nv_bfloat16 g_whi[(size_t)2560 * 512];
__device__ __nv_bfloat16 g_wlo[(size_t)2560 * 512];
// A concat: [mem 0-119|rc 120-631|utt 632-8823|summ 8824-8951|(gap)|pos 8960-9150]
__device__ __nv_bfloat16 g_ahi[(size_t)9216 * 512];
__device__ __nv_bfloat16 g_alo[(size_t)9216 * 512];
__device__ __nv_bfloat16 g_poshi[(size_t)256 * 512];
__device__ __nv_bfloat16 g_poslo[(size_t)256 * 512];
__device__ __nv_bfloat16 g_qhi[(size_t)Q_ * B_ * 512];
__device__ __nv_bfloat16 g_qlo[(size_t)Q_ * B_ * 512];
__device__ __nv_bfloat16 g_kvhi[(size_t)KV_ * B_ * 1024];
__device__ __nv_bfloat16 g_kvlo[(size_t)KV_ * B_ * 1024];

__device__ __forceinline__ int kv_row_of(int i, int c, int ustart) {
    return (i < c) ? i
         : (i < c + 4 ? M_ + c * 4 + (i - c)
                      : M_ + R_ + ustart + (i - c - 4));
}

// =====================================================================
// Mega conversion kernel (A concat + pos + all weights)
// =====================================================================
#define CONV_NA (8952 * 128)
#define CONV_NP (191 * 128)
#define CONV_NW (2560 * 512)
#define CONV_TOT (CONV_NA + CONV_NP + CONV_NW)

__global__ void conv_all_kernel(
    const float* __restrict__ utt, const float* __restrict__ rc,
    const float* __restrict__ summ, const float* __restrict__ mem,
    const float* __restrict__ pos_src,
    const float* __restrict__ Wq, const float* __restrict__ Wkv,
    const float* __restrict__ Wout, const float* __restrict__ Wpos)
{
    int i = blockIdx.x * 256 + threadIdx.x;
    if (i < CONV_NA + CONV_NP) {
        const float* src; int lr, drow, c4;
        if (i < CONV_NA) {
            int row = i >> 7; c4 = (i & 127) * 4;
            if (row < 120)       { src = mem;  lr = row; }
            else if (row < 632)  { src = rc;   lr = row - 120; }
            else if (row < 8824) { src = utt;  lr = row - 632; }
            else                 { src = summ; lr = row - 8824; }
            drow = row;
        } else {
            int j = i - CONV_NA;
            int row = j >> 7; c4 = (j & 127) * 4;
            src = pos_src; lr = row; drow = 8960 + row;
        }
        float4 v = *(const float4*)(src + (size_t)lr * 512 + c4);
        uint32_t h0, l0, h1, l1;
        pack_hl(v.x, v.y, h0, l0);
        pack_hl(v.z, v.w, h1, l1);
        size_t o = (size_t)drow * 512 + c4;
        *(uint2*)&g_ahi[o] = make_uint2(h0, h1);
        *(uint2*)&g_alo[o] = make_uint2(l0, l1);
    } else if (i < CONV_TOT) {
        int j = i - CONV_NA - CONV_NP;
        int row = j >> 9, col = j & 511;
        const float* src; int lr;
        if (row < 512)       { src = Wq;   lr = row; }
        else if (row < 1536) { src = Wkv;  lr = row - 512; }
        else if (row < 2048) { src = Wout; lr = row - 1536; }
        else                 { src = Wpos; lr = row - 2048; }
        float a = src[(size_t)lr * 512 + col];
        __nv_bfloat16 h = __float2bfloat16(a);
        g_whi[j] = h;
        g_wlo[j] = __float2bfloat16(a - __bfloat162float(h));
    }
}

// =====================================================================
// GEMM mainloop: 128x128 tile, cp.async 3-stage, 24 chunks
// =====================================================================
#define GSM_TOTAL 98304

#define GEMM_MAINLOOP(AHI, ALO, WHI, WLO, MRTOT)                                    \
    float acc[2][8][4] = {};                                                        \
    {                                                                               \
        auto issue = [&](int cc) {                                                  \
            const int seg = cc >> 3;                                                \
            const int k0 = (cc & 7) * 64;                                           \
            const __nv_bfloat16* asrc = (seg == 1) ? (ALO) : (AHI);                 \
            const __nv_bfloat16* wsrc = (seg == 2) ? (WLO) : (WHI);                 \
            char* abuf = gsm + (cc % 3) * 16384;                                    \
            char* bbuf = gsm + 49152 + (cc % 3) * 16384;                            \
            _Pragma("unroll")                                                       \
            for (int t = 0; t < 4; t++) {                                           \
                int ar = car + t * 32;                                              \
                int gr = row0 + ar; if (gr >= (MRTOT)) gr = (MRTOT) - 1;            \
                cpa16(smem_u32(abuf) + SWZ128((uint32_t)(ar * 128 + cg8 * 16)),     \
                      asrc + (size_t)gr * 512 + k0 + cg8 * 8);                      \
            }                                                                       \
            _Pragma("unroll")                                                       \
            for (int t = 0; t < 4; t++) {                                           \
                int br = car + t * 32;                                              \
                cpa16(smem_u32(bbuf) + SWZ128((uint32_t)(br * 128 + cg8 * 16)),     \
                      wsrc + (size_t)(col0 + br) * 512 + k0 + cg8 * 8);             \
            }                                                                       \
            CPA_COMMIT();                                                           \
        };                                                                          \
        issue(0);                                                                   \
        issue(1);                                                                   \
        const int l15 = lane & 15, lh = lane >> 4;                                  \
        const int l8 = lane & 7, lg = lane >> 3;                                    \
        for (int cc = 0; cc < 24; cc++) {                                           \
            if (cc < 23) CPA_WAIT1(); else CPA_WAIT0();                             \
            __syncthreads();                                                        \
            const uint32_t Ab = sb + (cc % 3) * 16384;                              \
            const uint32_t Bb = sb + 49152 + (cc % 3) * 16384;                      \
            _Pragma("unroll")                                                       \
            for (int s = 0; s < 4; s++) {                                           \
                uint32_t afr[2][4];                                                 \
                _Pragma("unroll")                                                   \
                for (int mt = 0; mt < 2; mt++) {                                    \
                    int r = wm * 32 + mt * 16 + l15;                                \
                    ldmx4(afr[mt], Ab + SWZ128((uint32_t)(r * 128 + s * 32 + lh * 16))); \
                }                                                                   \
                uint32_t bfr[4][4];                                                 \
                _Pragma("unroll")                                                   \
                for (int bt = 0; bt < 4; bt++) {                                    \
                    int n = wn * 64 + bt * 16 + ((lg >> 1) ? 8 : 0) + l8;           \
                    ldmx4(bfr[bt], Bb + SWZ128((uint32_t)(n * 128 + s * 32 + (lg & 1) * 16))); \
                }                                                                   \
                _Pragma("unroll")                                                   \
                for (int mt = 0; mt < 2; mt++)                                      \
                    _Pragma("unroll")                                               \
                    for (int nt = 0; nt < 8; nt++) {                                \
                        int bt = nt >> 1, sub = nt & 1;                             \
                        mma16816(acc[mt][nt], afr[mt], bfr[bt][2*sub], bfr[bt][2*sub+1]); \
                    }                                                               \
            }                                                                       \
            if (cc + 2 < 24) issue(cc + 2);                                         \
        }                                                                           \
    }

// ---- generic GEMM (out projection), fp32 out ----
__global__ __launch_bounds__(256, 2) void gemm_tc_kernel(
    const __nv_bfloat16* __restrict__ Ahi, const __nv_bfloat16* __restrict__ Alo,
    const __nv_bfloat16* __restrict__ Whib, const __nv_bfloat16* __restrict__ Wlob,
    float* __restrict__ Cm, int Mr, int ldc, const float* __restrict__ bias)
{
    extern __shared__ char gsm[];
    const uint32_t sb = smem_u32(gsm);
    const int tid = threadIdx.x;
    const int wid = tid >> 5, lane = tid & 31;
    const int wm = wid & 3, wn = wid >> 2;
    const int row0 = blockIdx.y * 128, col0 = blockIdx.x * 128;
    const int car = tid >> 3, cg8 = tid & 7;

    GEMM_MAINLOOP(Ahi, Alo, Whib, Wlob, Mr)

    const int quad = lane >> 2, tq = lane & 3;
    #pragma unroll
    for (int mt = 0; mt < 2; mt++) {
        #pragma unroll
        for (int nt = 0; nt < 8; nt++) {
            int gr0 = row0 + wm * 32 + mt * 16 + quad;
            int gc  = col0 + wn * 64 + nt * 8 + tq * 2;
            float b0 = bias ? bias[gc]     : 0.f;
            float b1 = bias ? bias[gc + 1] : 0.f;
            #pragma unroll
            for (int half = 0; half < 2; half++) {
                int gr = gr0 + half * 8;
                if (gr < Mr) {
                    float2 v = {acc[mt][nt][half*2+0] + b0, acc[mt][nt][half*2+1] + b1};
                    *(float2*)&Cm[(size_t)gr * ldc + gc] = v;
                }
            }
        }
    }
}

// ---- fused Q+KV(+pos) GEMM ----
__global__ __launch_bounds__(256, 2) void gemm_qkv_kernel(
    const float* __restrict__ b_q, const float* __restrict__ b_kv,
    const float* __restrict__ pbu)
{
    const int row0 = blockIdx.y * 128, col0 = blockIdx.x * 128;
    const bool is_pos = (blockIdx.y >= 70);
    if (is_pos && col0 >= 512) return;

    extern __shared__ char gsm[];
    const uint32_t sb = smem_u32(gsm);
    const int tid = threadIdx.x;
    const int wid = tid >> 5, lane = tid & 31;
    const int wm = wid & 3, wn = wid >> 2;
    const int car = tid >> 3, cg8 = tid & 7;

    const __nv_bfloat16* WHIp = g_whi + (is_pos ? (size_t)2048 * 512 : 0);
    const __nv_bfloat16* WLOp = g_wlo + (is_pos ? (size_t)2048 * 512 : 0);

    GEMM_MAINLOOP(g_ahi, g_alo, WHIp, WLOp, 9216)

    const int quad = lane >> 2, tq = lane & 3;
    if (is_pos) {
        #pragma unroll
        for (int mt = 0; mt < 2; mt++) {
            #pragma unroll
            for (int nt = 0; nt < 8; nt++) {
                int gr0 = row0 + wm * 32 + mt * 16 + quad;
                int gc  = col0 + wn * 64 + nt * 8 + tq * 2;
                #pragma unroll
                for (int half = 0; half < 2; half++) {
                    int pl = gr0 + half * 8 - 8960;
                    float2 v = {acc[mt][nt][half*2+0], acc[mt][nt][half*2+1]};
                    *(float2*)&g_pos[(size_t)pl * 512 + gc] = v;
                    uint32_t hi, lo;
                    pack_hl(v.x, v.y, hi, lo);
                    *(uint32_t*)&g_poshi[(size_t)pl * 512 + gc] = hi;
                    *(uint32_t*)&g_poslo[(size_t)pl * 512 + gc] = lo;
                }
            }
        }
        return;
    }

    const bool is_q = (col0 < 512);
    #pragma unroll
    for (int mt = 0; mt < 2; mt++) {
        #pragma unroll
        for (int nt = 0; nt < 8; nt++) {
            int gr0 = row0 + wm * 32 + mt * 16 + quad;
            int gc  = col0 + wn * 64 + nt * 8 + tq * 2;
            #pragma unroll
            for (int half = 0; half < 2; half++) {
                int gr = gr0 + half * 8;
                if (gr >= 8952) continue;
                float2 v = {acc[mt][nt][half*2+0], acc[mt][nt][half*2+1]};
                if (is_q) {
                    int qr = gr - 120;
                    if (qr >= 0) {
                        v.x += b_q[gc] + pbu[gc];
                        v.y += b_q[gc + 1] + pbu[gc + 1];
                        uint32_t hi, lo;
                        pack_hl(v.x, v.y, hi, lo);
                        *(uint32_t*)&g_qhi[(size_t)qr * 512 + gc] = hi;
                        *(uint32_t*)&g_qlo[(size_t)qr * 512 + gc] = lo;
                    }
                } else {
                    int kc = gc - 512;
                    if (gr < 8824) {
                        v.x += b_kv[kc]; v.y += b_kv[kc + 1];
                        uint32_t hi, lo;
                        pack_hl(v.x, v.y, hi, lo);
                        *(uint32_t*)&g_kvhi[(size_t)gr * 1024 + kc] = hi;
                        *(uint32_t*)&g_kvlo[(size_t)gr * 1024 + kc] = lo;
                    }
                }
            }
        }
    }
}

// =====================================================================
// ps kernel: compact band g_psc[bh][u][j] = (q+pbu).pos[pbase-u_loc+uc0+j]
//            + (pbv-pbu).pos[...], j = i - uc0 (i.e. local utt column).
// dvp computed in-kernel while cp.asyncs are in flight.
// =====================================================================
#define PS_DVP 65536
#define PS_TOTAL (65536 + 768)

__global__ __launch_bounds__(256) void ps_kernel(
    const float* __restrict__ pbu, const float* __restrict__ pbv)
{
    extern __shared__ char psm[];
    const uint32_t sb = smem_u32(psm);
    float* dvp_s = (float*)(psm + PS_DVP);
    const int ut = blockIdx.x, bh = blockIdx.y;
    const int b = bh >> 3, h = bh & 7;
    const int tid = threadIdx.x;
    const int wid = tid >> 5, lane = tid & 31;
    const int pbase = (ut == 0) ? 127 : 63;

    for (int idx = tid; idx < 192 * 8; idx += 256) {
        int r = idx >> 3, ch = idx & 7;
        size_t go = (size_t)r * 512 + h * 64 + ch * 8;
        uint32_t so = SWZ128((uint32_t)(r * 128 + ch * 16));
        cpa16(sb + 16384 + so, g_poshi + go);
        cpa16(sb + 40960 + so, g_poslo + go);
    }
    for (int idx = tid; idx < 64 * 8; idx += 256) {
        int r = idx >> 3, ch = idx & 7;
        int qrow = R_ + ut * 64 + r;
        size_t go = ((size_t)qrow * B_ + b) * 512 + h * 64 + ch * 8;
        uint32_t so = SWZ128((uint32_t)(r * 128 + ch * 16));
        cpa16(sb + so, g_qhi + go);
        cpa16(sb + 8192 + so, g_qlo + go);
    }
    CPA_COMMIT();

    if (tid < 192) {
        int pl = tid;
        float s = 0.f;
        const float4* pp = (const float4*)(g_pos + (size_t)pl * 512 + h * 64);
        const float4* up = (const float4*)(pbu + h * 64);
        const float4* vp = (const float4*)(pbv + h * 64);
        #pragma unroll 4
        for (int k4 = 0; k4 < 16; k4++) {
            float4 a = pp[k4], uu = up[k4], vv = vp[k4];
            s += a.x * (vv.x - uu.x) + a.y * (vv.y - uu.y)
               + a.z * (vv.z - uu.z) + a.w * (vv.w - uu.w);
        }
        dvp_s[pl] = s;
    }
    CPA_WAIT0();
    __syncthreads();

    const int wm = wid >> 2, wn = wid & 3;
    const int l15 = lane & 15, lh = lane >> 4;
    const int l8 = lane & 7, lg = lane >> 3;
    const int quad = lane >> 2, tq = lane & 3;

    float acc[2][3][2][4] = {};
    #pragma unroll
    for (int pass = 0; pass < 3; pass++) {
        const uint32_t Ab = sb + ((pass == 1) ? 8192 : 0);
        const uint32_t Bb = sb + ((pass == 2) ? 40960 : 16384);
        #pragma unroll
        for (int s = 0; s < 4; s++) {
            uint32_t afr[2][4];
            #pragma unroll
            for (int mi = 0; mi < 2; mi++) {
                int r = (wm * 2 + mi) * 16 + l15;
                ldmx4(afr[mi], Ab + SWZ128((uint32_t)(r * 128 + s * 32 + lh * 16)));
            }
            #pragma unroll
            for (int nj = 0; nj < 3; nj++) {
                uint32_t bfr[4];
                int n = (wn + 4 * nj) * 16 + ((lg >> 1) ? 8 : 0) + l8;
                ldmx4(bfr, Bb + SWZ128((uint32_t)(n * 128 + s * 32 + (lg & 1) * 16)));
                #pragma unroll
                for (int mi = 0; mi < 2; mi++) {
                    mma16816(acc[mi][nj][0], afr[mi], bfr[0], bfr[1]);
                    mma16816(acc[mi][nj][1], afr[mi], bfr[2], bfr[3]);
                }
            }
        }
    }
    // epilogue -> compact g_psc: j = col - pbase + u_loc, store if 0<=j<128
    #pragma unroll
    for (int mi = 0; mi < 2; mi++) {
        #pragma unroll
        for (int nj = 0; nj < 3; nj++) {
            #pragma unroll
            for (int nh = 0; nh < 2; nh++) {
                int col = (wn + 4 * nj) * 16 + nh * 8 + tq * 2;
                float2 dv = *(const float2*)&dvp_s[col];
                #pragma unroll
                for (int hf = 0; hf < 2; hf++) {
                    int u_loc = (wm * 2 + mi) * 16 + quad + hf * 8;
                    int u = ut * 64 + u_loc;
                    int j = col - pbase + u_loc;
                    float* dst = &g_psc[((size_t)bh * 1024 + u) * 128];
                    if (j >= 0 && j < 128)
                        dst[j] = acc[mi][nj][nh][hf * 2 + 0] + dv.x;
                    if (j + 1 >= 0 && j + 1 < 128)
                        dst[j + 1] = acc[mi][nj][nh][hf * 2 + 1] + dv.y;
                }
            }
        }
    }
}

// =====================================================================
// Fused attention v10: compact band (contiguous rows, batched loads).
// 512 threads, 113280B smem -> 2 CTAs/SM.
// =====================================================================
#define FZ_QHI 0
#define FZ_QLO 10240
#define FZ_KHI 20480
#define FZ_KLO 40960
#define FZ_SS  61440
#define FZ_PHI 61440
#define FZ_PLO 84624
#define FZ_TOTAL 113280

__global__ __launch_bounds__(512, 2) void fused_attn_kernel(
    const int* __restrict__ lengths, float* __restrict__ outp)
{
    extern __shared__ char fsm[];
    const uint32_t sb = smem_u32(fsm);

    const int c = blockIdx.x, bh = blockIdx.y;
    const int b = bh >> 3, h = bh & 7;
    const int tid = threadIdx.x;
    const int wid = tid >> 5, lane = tid & 31;
    const int ustart = (c == 0) ? 0 : (c - 1) * CL_;
    const int ncols = c + 4 + ((c == 0) ? 64 : 128);
    const int ntiles = (ncols + 15) >> 4;
    const int len_b = lengths[b];

    for (int idx = tid; idx < 69 * 8; idx += 512) {
        int r = idx >> 3, ch = idx & 7;
        int qrow = (r < 4) ? c * 4 + r
                 : (r < 68 ? R_ + c * 64 + (r - 4) : R_ + U_ + c);
        size_t go = ((size_t)qrow * B_ + b) * 512 + h * 64 + ch * 8;
        uint32_t so = SWZ128((uint32_t)(r * 128 + ch * 16));
        cpa16(sb + FZ_QHI + so, g_qhi + go);
        cpa16(sb + FZ_QLO + so, g_qlo + go);
    }
    for (int idx = tid; idx < ncols * 8; idx += 512) {
        int r = idx >> 3, ch = idx & 7;
        int kvrow = kv_row_of(r, c, ustart);
        size_t go = ((size_t)kvrow * B_ + b) * 1024 + h * 64 + ch * 8;
        uint32_t so = SWZ128((uint32_t)(r * 128 + ch * 16));
        cpa16(sb + FZ_KHI + so, g_kvhi + go);
        cpa16(sb + FZ_KLO + so, g_kvlo + go);
    }
    {
        uint4 z = make_uint4(0, 0, 0, 0);
        int npad = ntiles * 16 - ncols;
        for (int idx = tid; idx < npad * 8; idx += 512) {
            int r = ncols + (idx >> 3), ch = idx & 7;
            uint32_t so = SWZ128((uint32_t)(r * 128 + ch * 16));
            *(uint4*)(fsm + FZ_KHI + so) = z;
            *(uint4*)(fsm + FZ_KLO + so) = z;
        }
    }
    CPA_COMMIT();
    CPA_WAIT0();
    __syncthreads();

    const int l15 = lane & 15, lh = lane >> 4;
    const int l8 = lane & 7, lg = lane >> 3;
    const int quad = lane >> 2, tq = lane & 3;
    const int wmc = wid / 3, wnc = wid % 3;

    // ---- C1: scores = (Q+pbu).K^T ----
    if (wmc < 5) {
        float acc[4][2][4] = {};
        #pragma unroll
        for (int pass = 0; pass < 3; pass++) {
            const uint32_t Ab = sb + ((pass == 1) ? FZ_QLO : FZ_QHI);
            const uint32_t Bb = sb + ((pass == 2) ? FZ_KLO : FZ_KHI);
            #pragma unroll
            for (int s = 0; s < 4; s++) {
                uint32_t afr[4];
                ldmx4(afr, Ab + SWZ128((uint32_t)((wmc * 16 + l15) * 128 + s * 32 + lh * 16)));
                #pragma unroll
                for (int nj = 0; nj < 4; nj++) {
                    int nt = wnc + 3 * nj;
                    if (nt < ntiles) {
                        uint32_t bfr[4];
                        int n = nt * 16 + ((lg >> 1) ? 8 : 0) + l8;
                        ldmx4(bfr, Bb + SWZ128((uint32_t)(n * 128 + s * 32 + (lg & 1) * 16)));
                        mma16816(acc[nj][0], afr, bfr[0], bfr[1]);
                        mma16816(acc[nj][1], afr, bfr[2], bfr[3]);
                    }
                }
            }
        }
        #pragma unroll
        for (int nj = 0; nj < 4; nj++) {
            int nt = wnc + 3 * nj;
            if (nt < ntiles) {
                int r0 = wmc * 16 + quad;
                #pragma unroll
                for (int hf = 0; hf < 2; hf++) {
                    int col = nt * 16 + hf * 8 + tq * 2;
                    *(float2*)(fsm + FZ_SS + (size_t)r0 * 648 + col * 4) =
                        make_float2(acc[nj][hf][0], acc[nj][hf][1]);
                    *(float2*)(fsm + FZ_SS + (size_t)(r0 + 8) * 648 + col * 4) =
                        make_float2(acc[nj][hf][2], acc[nj][hf][3]);
                }
            }
        }
    }
    __syncthreads();

    // ---- V load (overwrites K) + zero partial pad ----
    {
        uint4 z = make_uint4(0, 0, 0, 0);
        int npad = ntiles * 16 - ncols;
        for (int idx = tid; idx < npad * 8; idx += 512) {
            int r = ncols + (idx >> 3), ch = idx & 7;
            uint32_t so = SWZ128((uint32_t)(r * 128 + ch * 16));
            *(uint4*)(fsm + FZ_KHI + so) = z;
            *(uint4*)(fsm + FZ_KLO + so) = z;
        }
        for (int idx = tid; idx < ncols * 8; idx += 512) {
            int r = idx >> 3, ch = idx & 7;
            int kvrow = kv_row_of(r, c, ustart);
            size_t go = ((size_t)kvrow * B_ + b) * 1024 + 512 + h * 64 + ch * 8;
            uint32_t so = SWZ128((uint32_t)(r * 128 + ch * 16));
            cpa16(sb + FZ_KHI + so, g_kvhi + go);
            cpa16(sb + FZ_KLO + so, g_kvlo + go);
        }
        CPA_COMMIT();
    }

    // ---- softmax phase A: batched band loads, then combine ----
    float pvals[5][5];
    {
        const int limit_j = len_b - ustart;
        const int uc0 = c + 4;
        int slot = 0;
        for (int r = wid; r < 69; r += 16, slot++) {
            const bool is_utt = (r >= 4) && (r < 68);
            const float* pscrow = g_psc + ((size_t)bh * 1024 + c * 64 + (r - 4)) * 128;
            // batched band loads first (MLP 5)
            float bd[5];
            #pragma unroll
            for (int g = 0; g < 5; g++) {
                int i = lane + 32 * g;
                int j = i - uc0;
                bd[g] = (is_utt && (unsigned)j < 128u) ? pscrow[j] : 0.f;
            }
            float vals[5];
            float mx = -3.4e38f;
            #pragma unroll
            for (int g = 0; g < 5; g++) {
                int i = lane + 32 * g;
                float v = -3.4e38f;
                if (i < ncols) {
                    float s = *(const float*)(fsm + FZ_SS + (size_t)r * 648 + i * 4);
                    if (i >= uc0) {
                        int j = i - uc0;
                        s += bd[g];
                        v = (j >= limit_j) ? NEG_INF_ : s * SCALING_;
                    } else {
                        v = s * SCALING_;
                    }
                }
                vals[g] = v;
                mx = fmaxf(mx, v);
            }
            #pragma unroll
            for (int o = 16; o > 0; o >>= 1) mx = fmaxf(mx, __shfl_xor_sync(~0u, mx, o));
            float sum = 0.f;
            #pragma unroll
            for (int g = 0; g < 5; g++) {
                float e = __expf(vals[g] - mx);
                vals[g] = e;
                sum += e;
            }
            #pragma unroll
            for (int o = 16; o > 0; o >>= 1) sum += __shfl_xor_sync(~0u, sum, o);
            float inv = 1.f / sum;
            #pragma unroll
            for (int g = 0; g < 5; g++) pvals[slot][g] = vals[g] * inv;
        }
    }
    __syncthreads();

    // ---- phase B: write P bf16 hi/lo over dead score region ----
    {
        int slot = 0;
        for (int r = wid; r < 69; r += 16, slot++) {
            #pragma unroll
            for (int g = 0; g < 5; g++) {
                int i = lane + 32 * g;
                float p = (i < ncols) ? pvals[slot][g] : 0.f;
                __nv_bfloat16 hp = __float2bfloat16(p);
                __nv_bfloat16 lp = __float2bfloat16(p - __bfloat162float(hp));
                *(ushort*)(fsm + FZ_PHI + r * 336 + i * 2) = __bfloat16_as_ushort(hp);
                *(ushort*)(fsm + FZ_PLO + r * 336 + i * 2) = __bfloat16_as_ushort(lp);
            }
        }
    }
    CPA_WAIT0();
    __syncthreads();

    // ---- PV: out = P.V ----
    {
        const int wmp = wid >> 2, wnp = wid & 3;
        float accp[2][2][4] = {};
        #pragma unroll
        for (int pass = 0; pass < 3; pass++) {
            const uint32_t Ab = sb + ((pass == 1) ? FZ_PLO : FZ_PHI);
            const uint32_t Bb = sb + ((pass == 2) ? FZ_KLO : FZ_KHI);
            for (int kk = 0; kk < ntiles; kk++) {
                uint32_t bfr[4];
                ldmx4t(bfr, Bb + SWZ128((uint32_t)((kk * 16 + l15) * 128 + wnp * 32 + lh * 16)));
                #pragma unroll
                for (int mi = 0; mi < 2; mi++) {
                    int m = wmp + 4 * mi;
                    if (m < 5) {
                        uint32_t afr[4];
                        ldmx4(afr, Ab + (uint32_t)((m * 16 + l15) * 336 + kk * 32 + lh * 16));
                        mma16816(accp[mi][0], afr, bfr[0], bfr[1]);
                        mma16816(accp[mi][1], afr, bfr[2], bfr[3]);
                    }
                }
            }
        }
        #pragma unroll
        for (int mi = 0; mi < 2; mi++) {
            int m = wmp + 4 * mi;
            if (m >= 5) continue;
            int r0 = m * 16 + quad;
            #pragma unroll
            for (int hf = 0; hf < 2; hf++) {
                int r = r0 + hf * 8;
                if (r < 68) {
                    int qrow = (r < 4) ? c * 4 + r : R_ + c * 64 + (r - 4);
                    size_t base = ((size_t)qrow * B_ + b) * 512 + h * 64;
                    #pragma unroll
                    for (int n = 0; n < 2; n++) {
                        int d = wnp * 16 + n * 8 + tq * 2;
                        uint32_t vhi, vlo;
                        pack_hl(accp[mi][n][hf*2+0], accp[mi][n][hf*2+1], vhi, vlo);
                        *(uint32_t*)&g_ahi[base + d] = vhi;
                        *(uint32_t*)&g_alo[base + d] = vlo;
                    }
                } else if (r == 68) {
                    int qrow = R_ + U_ + c;
                    float* dst = outp + ((size_t)qrow * B_ + b) * 512 + h * 64;
                    #pragma unroll
                    for (int n = 0; n < 2; n++) {
                        int d = wnp * 16 + n * 8 + tq * 2;
                        float2 v = {accp[mi][n][hf*2+0], accp[mi][n][hf*2+1]};
                        v.x = fminf(10.f, fmaxf(-10.f, v.x));
                        v.y = fminf(10.f, fmaxf(-10.f, v.y));
                        *(float2*)(dst + d) = v;
                    }
                }
            }
        }
    }
}

// ---------------- launch ----------------
extern "C" void kernel_launch(void* const* d_in, const int* in_sizes, int n_in,
                              void* d_out, int out_size)
{
    const float* utt    = (const float*)d_in[0];
    const int*   lens   = (const int*)  d_in[1];
    const float* rc     = (const float*)d_in[2];
    const float* summ   = (const float*)d_in[3];
    const float* mem    = (const float*)d_in[4];
    const float* pos_e  = (const float*)d_in[6];
    const float* W_kv   = (const float*)d_in[7];
    const float* b_kv   = (const float*)d_in[8];
    const float* W_q    = (const float*)d_in[9];
    const float* b_q    = (const float*)d_in[10];
    const float* W_out  = (const float*)d_in[11];
    const float* b_out  = (const float*)d_in[12];
    const float* W_pos  = (const float*)d_in[13];
    const float* pbu    = (const float*)d_in[14];
    const float* pbv    = (const float*)d_in[15];
    float* out = (float*)d_out;

    __nv_bfloat16 *ahi, *alo, *whi, *wlo;
    cudaGetSymbolAddress((void**)&ahi, g_ahi);
    cudaGetSymbolAddress((void**)&alo, g_alo);
    cudaGetSymbolAddress((void**)&whi, g_whi);
    cudaGetSymbolAddress((void**)&wlo, g_wlo);

    cudaFuncSetAttribute(fused_attn_kernel,
                         cudaFuncAttributeMaxDynamicSharedMemorySize, FZ_TOTAL);
    cudaFuncSetAttribute(ps_kernel,
                         cudaFuncAttributeMaxDynamicSharedMemorySize, PS_TOTAL);
    cudaFuncSetAttribute(gemm_tc_kernel,
                         cudaFuncAttributeMaxDynamicSharedMemorySize, GSM_TOTAL);
    cudaFuncSetAttribute(gemm_qkv_kernel,
                         cudaFuncAttributeMaxDynamicSharedMemorySize, GSM_TOTAL);

    const dim3 blk(256);
    const float* pos_src = pos_e + (size_t)(U_ - 128) * D_;

    // ---- all conversions in one launch ----
    conv_all_kernel<<<dim3((CONV_TOT + 255) / 256), blk>>>(
        utt, rc, summ, mem, pos_src, W_q, W_kv, W_out, W_pos);

    // ---- fused Q+KV+pos projection ----
    gemm_qkv_kernel<<<dim3(12, 72), blk, GSM_TOTAL>>>(b_q, b_kv, pbu);

    // ---- compact band, fused attention ----
    ps_kernel<<<dim3(16, 64), blk, PS_TOTAL>>>(pbu, pbv);
    fused_attn_kernel<<<dim3(C_, 64), dim3(512), FZ_TOTAL>>>(lens, out);

    // ---- output projection ----
    gemm_tc_kernel<<<dim3(4, 68), blk, GSM_TOTAL>>>(
        ahi, alo, whi + (size_t)1536 * 512, wlo + (size_t)1536 * 512,
        out, (R_ + U_) * B_, D_, b_out);
}